// round 7
// baseline (speedup 1.0000x reference)
#include <cuda_runtime.h>
#include <cuda_fp16.h>
#include <cstdint>

#define BATCH 4
#define T 4096
#define D 1024
#define H 64
#define MTOT (BATCH * T)

// ---------------------------------------------------------------------------
// Packed fp16 split streams (fully contiguous K', chunks pre-duplicated):
//   3-term: A chunks [hi|hi|lo], B chunks [hi|lo|hi]
//           => A'.B'^T = Ahi.Bhi + Ahi.Blo + Alo.Bhi   (~2^-22)
//   2-term: A chunks [hi|lo],    B chunks [hi|hi]
//           => (Ahi+Alo).Bhi                            (~2^-12)
// ---------------------------------------------------------------------------
__device__ __align__(256) __half g_xA3[(size_t)MTOT * 3 * D];        // 96 MB (QK-proj A)
__device__ __align__(256) __half g_xB2[(size_t)MTOT * 2 * D];        // 64 MB (V-proj B)
__device__ __align__(256) __half g_wqkB3[128 * 3 * D];               // .75 MB
__device__ __align__(256) __half g_wvA2[(size_t)D * 2 * D];          // 4 MB
__device__ __align__(256) float  g_qk[(size_t)MTOT * 128];           // 8 MB
__device__ __align__(256) __half g_qA3[(size_t)MTOT * 192];          // 6 MB
__device__ __align__(256) __half g_kB3[(size_t)MTOT * 192];          // 6 MB
__device__ __align__(256) float  g_vt[(size_t)D * MTOT];             // 64 MB (V^T fp32)
__device__ __align__(256) __half g_vtB2[(size_t)BATCH * D * 2 * T];  // 64 MB
__device__ __align__(256) float  g_S[(size_t)BATCH * T * T];         // 256 MB
__device__ __align__(256) __half g_pA2[(size_t)BATCH * T * 2 * T];   // 256 MB

// ---------------------------------------------------------------------------
// Pack: split src into fp16 hi/lo, chunk-duplicated layout per mode.
// mode 0: [hi|hi|lo] (3A)   mode 1: [hi|lo|hi] (3B)
// mode 2: [hi|lo]    (2A)   mode 3: [hi|hi]    (2B)
// ---------------------------------------------------------------------------
__global__ __launch_bounds__(256)
void packN(const float* __restrict__ src, int ldsrc, int col0, int ncols,
           __half* __restrict__ dst, int mode, float scale, int total) {
    int idx = blockIdx.x * 256 + threadIdx.x;
    if (idx >= total) return;
    int row = idx / ncols;
    int k = idx - row * ncols;
    float v = src[(size_t)row * ldsrc + col0 + k] * scale;
    __half hi = __float2half_rn(v);
    __half lo = __float2half_rn(v - __half2float(hi));
    int c = k >> 6, o = k & 63;
    if (mode <= 1) {
        size_t base = (size_t)row * (3 * ncols) + (size_t)c * 192 + o;
        dst[base] = hi;
        dst[base + 64]  = (mode == 1) ? lo : hi;
        dst[base + 128] = (mode == 1) ? hi : lo;
    } else {
        size_t base = (size_t)row * (2 * ncols) + (size_t)c * 128 + o;
        dst[base] = hi;
        dst[base + 64] = (mode == 3) ? hi : lo;
    }
}

// ---------------------------------------------------------------------------
// HMMA fp16 GEMM: C[M,N] = A'[M,K'] * B'[N,K']^T (both K'-contiguous streams).
// 128x128x32 CTA tile, 8 warps 4(M)x2(N), warp tile 32x64.
// 2-stage cp.async double buffer (R5-proven structure).
// CAUSAL: skip tiles bx > by.  KLIMIT: nc = 8*(by+1) (2-term P@V causal).
// ---------------------------------------------------------------------------
#define ASTRIDE 80                          // bytes per 32-half smem row (64B + 16B pad)
#define TILE_BYTES (128 * ASTRIDE)          // 10240
#define STAGE_BYTES (2 * TILE_BYTES)        // A + B

__device__ __forceinline__ uint32_t smem_u32(const void* p) {
    uint32_t a;
    asm("{ .reg .u64 t; cvta.to.shared.u64 t, %1; cvt.u32.u64 %0, t; }" : "=r"(a) : "l"(p));
    return a;
}
__device__ __forceinline__ void cp16(uint32_t dst, const void* src) {
    asm volatile("cp.async.cg.shared.global [%0], [%1], 16;" :: "r"(dst), "l"(src));
}
__device__ __forceinline__ void ldm_x4(uint32_t* r, uint32_t addr) {
    asm volatile("ldmatrix.sync.aligned.m8n8.x4.shared.b16 {%0,%1,%2,%3}, [%4];"
                 : "=r"(r[0]), "=r"(r[1]), "=r"(r[2]), "=r"(r[3]) : "r"(addr));
}
__device__ __forceinline__ void mma16816(float* d, const uint32_t* a, const uint32_t* b) {
    asm volatile(
        "mma.sync.aligned.m16n8k16.row.col.f32.f16.f16.f32 "
        "{%0,%1,%2,%3}, {%4,%5,%6,%7}, {%8,%9}, {%0,%1,%2,%3};"
        : "+f"(d[0]), "+f"(d[1]), "+f"(d[2]), "+f"(d[3])
        : "r"(a[0]), "r"(a[1]), "r"(a[2]), "r"(a[3]), "r"(b[0]), "r"(b[1]));
}

template<bool CAUSAL, bool KLIMIT>
__global__ __launch_bounds__(256)
void gemm_hmma(const __half* __restrict__ A, const __half* __restrict__ B,
               float* __restrict__ C, int lda, int ldb, int ldc, int NC,
               size_t sA, size_t sB, size_t sC) {
    const int bx = blockIdx.x, by = blockIdx.y, bz = blockIdx.z;
    if (CAUSAL && bx > by) return;
    A += (size_t)bz * sA;
    B += (size_t)bz * sB;
    C += (size_t)bz * sC;
    const int row0 = by * 128, col0 = bx * 128;
    const int nc = KLIMIT ? min(NC, 8 * (by + 1)) : NC;

    __shared__ __align__(128) char smem[2 * STAGE_BYTES];   // 40 KB
    const uint32_t sbase = smem_u32(smem);

    const int tid = threadIdx.x;
    const int lane = tid & 31;
    const int w = tid >> 5;
    const int wm = (w & 3) * 32;       // warp m offset
    const int wn = (w >> 2) * 64;      // warp n offset

    // cp.async mapping: thread -> (tile row, 32B half of the 64B row)
    const int lr = tid >> 1;
    const int lh = (tid & 1);
    const __half* Ap = A + (size_t)(row0 + lr) * lda + lh * 16;
    const __half* Bp = B + (size_t)(col0 + lr) * ldb + lh * 16;
    const uint32_t dstRow = lr * ASTRIDE + lh * 32;

    // ldmatrix base addresses
    uint32_t aoff[2];
#pragma unroll
    for (int mt = 0; mt < 2; mt++)
        aoff[mt] = (uint32_t)((wm + mt * 16 + (lane & 15)) * ASTRIDE + ((lane >> 4) * 16));
    uint32_t boff[4];
#pragma unroll
    for (int nt2 = 0; nt2 < 4; nt2++)
        boff[nt2] = (uint32_t)((wn + nt2 * 16 + (lane & 7) + ((lane >> 4) & 1) * 8) * ASTRIDE
                               + (((lane >> 3) & 1) * 16));

    float acc[2][8][4];
#pragma unroll
    for (int mt = 0; mt < 2; mt++)
#pragma unroll
        for (int nt = 0; nt < 8; nt++)
#pragma unroll
            for (int q = 0; q < 4; q++) acc[mt][nt][q] = 0.f;

    // prologue: chunk 0 into stage 0
    {
        uint32_t ad = sbase + dstRow;
        uint32_t bd = sbase + TILE_BYTES + dstRow;
        cp16(ad, Ap);       cp16(ad + 16, Ap + 8);
        cp16(bd, Bp);       cp16(bd + 16, Bp + 8);
        asm volatile("cp.async.commit_group;" ::: "memory");
    }

    int buf = 0;
    for (int kc = 0; kc < nc; kc++) {
        if (kc + 1 < nc) {
            const __half* a2 = Ap + (size_t)(kc + 1) * 32;
            const __half* b2 = Bp + (size_t)(kc + 1) * 32;
            uint32_t st = sbase + (buf ^ 1) * STAGE_BYTES;
            cp16(st + dstRow, a2);                    cp16(st + dstRow + 16, a2 + 8);
            cp16(st + TILE_BYTES + dstRow, b2);       cp16(st + TILE_BYTES + dstRow + 16, b2 + 8);
            asm volatile("cp.async.commit_group;" ::: "memory");
            asm volatile("cp.async.wait_group 1;" ::: "memory");
        } else {
            asm volatile("cp.async.wait_group 0;" ::: "memory");
        }
        __syncthreads();

        const uint32_t abase = sbase + buf * STAGE_BYTES;
        const uint32_t bbase = abase + TILE_BYTES;
#pragma unroll
        for (int k16 = 0; k16 < 2; k16++) {
            const uint32_t ko = k16 * 32;
            uint32_t afr[2][4];
            ldm_x4(afr[0], abase + aoff[0] + ko);
            ldm_x4(afr[1], abase + aoff[1] + ko);
            uint32_t bfr[8][2];
#pragma unroll
            for (int nt2 = 0; nt2 < 4; nt2++) {
                uint32_t r[4];
                ldm_x4(r, bbase + boff[nt2] + ko);
                bfr[2 * nt2][0] = r[0];     bfr[2 * nt2][1] = r[1];
                bfr[2 * nt2 + 1][0] = r[2]; bfr[2 * nt2 + 1][1] = r[3];
            }
#pragma unroll
            for (int mt = 0; mt < 2; mt++)
#pragma unroll
                for (int nt = 0; nt < 8; nt++)
                    mma16816(acc[mt][nt], afr[mt], bfr[nt]);
        }
        __syncthreads();
        buf ^= 1;
    }

    // epilogue
    const int rq = lane >> 2;
    const int cq = (lane & 3) * 2;
#pragma unroll
    for (int mt = 0; mt < 2; mt++) {
#pragma unroll
        for (int nt = 0; nt < 8; nt++) {
            float* p = C + (size_t)(row0 + wm + mt * 16 + rq) * ldc + col0 + wn + nt * 8 + cq;
            p[0] = acc[mt][nt][0];
            p[1] = acc[mt][nt][1];
            float* p2 = p + 8 * (size_t)ldc;
            p2[0] = acc[mt][nt][2];
            p2[1] = acc[mt][nt][3];
        }
    }
}

// ---------------------------------------------------------------------------
// Causal softmax: fp32 scores row -> 2-term A-layout P row ([hi|lo] per 64).
// Only writes packed cols the P@V GEMM will read (<= causal K-limit tile).
// ---------------------------------------------------------------------------
__global__ __launch_bounds__(256)
void softmax_split(const float* __restrict__ S, __half* __restrict__ P) {
    const int i = blockIdx.x;
    const int b = blockIdx.y;
    const float* row = S + ((size_t)b * T + i) * (size_t)T;
    __half* prow = P + ((size_t)b * T + i) * (size_t)(2 * T);
    const int tid = threadIdx.x;
    const int len = i + 1;
    const int jmax = ((i >> 7) + 1) << 7;   // K-limit of this row's tile

    constexpr int R = T / 256;
    float local[R];
    float m = -3.4e38f;
#pragma unroll
    for (int r = 0; r < R; r++) {
        int j = r * 256 + tid;
        float v = (j < len) ? row[j] : -3.4e38f;
        local[r] = v;
        m = fmaxf(m, v);
    }
    __shared__ float red[8];
#pragma unroll
    for (int o = 16; o; o >>= 1) m = fmaxf(m, __shfl_xor_sync(0xffffffffu, m, o));
    if ((tid & 31) == 0) red[tid >> 5] = m;
    __syncthreads();
    m = red[0];
#pragma unroll
    for (int w = 1; w < 8; w++) m = fmaxf(m, red[w]);
    __syncthreads();

    float s = 0.f;
#pragma unroll
    for (int r = 0; r < R; r++) {
        int j = r * 256 + tid;
        float e = (j < len) ? __expf(local[r] - m) : 0.f;
        local[r] = e;
        s += e;
    }
#pragma unroll
    for (int o = 16; o; o >>= 1) s += __shfl_xor_sync(0xffffffffu, s, o);
    if ((tid & 31) == 0) red[tid >> 5] = s;
    __syncthreads();
    s = red[0];
#pragma unroll
    for (int w = 1; w < 8; w++) s += red[w];

    const float inv = 1.f / s;
#pragma unroll
    for (int r = 0; r < R; r++) {
        int j = r * 256 + tid;
        if (j < jmax) {
            float p = local[r] * inv;
            __half hi = __float2half_rn(p);
            __half lo = __float2half_rn(p - __half2float(hi));
            size_t base = (size_t)(j >> 6) * 128 + (j & 63);
            prow[base] = hi;
            prow[base + 64] = lo;
        }
    }
}

// ---------------------------------------------------------------------------
// kernel_launch
// ---------------------------------------------------------------------------
extern "C" void kernel_launch(void* const* d_in, const int* in_sizes, int n_in,
                              void* d_out, int out_size) {
    const float* x  = (const float*)d_in[0];
    const float* Wk = (const float*)d_in[1];
    const float* Wq = (const float*)d_in[2];
    const float* Wv = (const float*)d_in[3];
    float* out = (float*)d_out;

    __half *xA3, *xB2, *wqkB3, *wvA2, *qA3, *kB3, *vtB2, *pA2;
    float *qk, *vt, *S;
    cudaGetSymbolAddress((void**)&xA3, g_xA3);
    cudaGetSymbolAddress((void**)&xB2, g_xB2);
    cudaGetSymbolAddress((void**)&wqkB3, g_wqkB3);
    cudaGetSymbolAddress((void**)&wvA2, g_wvA2);
    cudaGetSymbolAddress((void**)&qk, g_qk);
    cudaGetSymbolAddress((void**)&qA3, g_qA3);
    cudaGetSymbolAddress((void**)&kB3, g_kB3);
    cudaGetSymbolAddress((void**)&vt, g_vt);
    cudaGetSymbolAddress((void**)&vtB2, g_vtB2);
    cudaGetSymbolAddress((void**)&S, g_S);
    cudaGetSymbolAddress((void**)&pA2, g_pA2);

    // 1) input packs
    packN<<<(MTOT * D + 255) / 256, 256>>>(x, D, 0, D, xA3, 0, 1.f, MTOT * D);   // 3A
    packN<<<(MTOT * D + 255) / 256, 256>>>(x, D, 0, D, xB2, 3, 1.f, MTOT * D);   // 2B
    packN<<<(64 * D + 255) / 256, 256>>>(Wq, D, 0, D, wqkB3, 1, 1.f, 64 * D);    // 3B
    packN<<<(64 * D + 255) / 256, 256>>>(Wk, D, 0, D, wqkB3 + (size_t)64 * 3 * D, 1, 1.f, 64 * D);
    packN<<<(D * D + 255) / 256, 256>>>(Wv, D, 0, D, wvA2, 2, 1.f, D * D);       // 2A

    // 2) QK projection (3-term): xA3[16384,3072] x wqkB3[128,3072]^T -> qk fp32
    gemm_hmma<false, false><<<dim3(1, MTOT / 128, 1), 256>>>(
        xA3, wqkB3, qk, 3 * D, 3 * D, 128, 96, 0, 0, 0);

    // 3) V^T projection (2-term): wvA2[1024,2048] x xB2[16384,2048]^T -> vt [1024,16384]
    gemm_hmma<false, false><<<dim3(MTOT / 128, D / 128, 1), 256>>>(
        wvA2, xB2, vt, 2 * D, 2 * D, MTOT, 64, 0, 0, 0);

    // 4) split-pack Q (pre-scaled 1/8, 3A), K (3B), V^T (2B)
    packN<<<(MTOT * 64 + 255) / 256, 256>>>(qk, 128, 0, 64, qA3, 0, 0.125f, MTOT * 64);
    packN<<<(MTOT * 64 + 255) / 256, 256>>>(qk, 128, 64, 64, kB3, 1, 1.f, MTOT * 64);
    for (int b = 0; b < BATCH; b++) {
        packN<<<(D * T + 255) / 256, 256>>>(
            vt, MTOT, b * T, T, vtB2 + (size_t)b * D * 2 * T, 3, 1.f, D * T);
    }

    // 5) scores (3-term, causal tile skip): S[b] = Qs K^T
    gemm_hmma<true, false><<<dim3(T / 128, T / 128, BATCH), 256>>>(
        qA3, kB3, S, 192, 192, T, 6,
        (size_t)T * 192, (size_t)T * 192, (size_t)T * T);

    // 6) softmax -> 2-term split P (writes only the causally-read region)
    softmax_split<<<dim3(T, BATCH), 256>>>(S, pA2);

    // 7) out[b] = P[b] @ V[b] (2-term, causal K-limit)
    gemm_hmma<false, true><<<dim3(D / 128, T / 128, BATCH), 256>>>(
        pA2, vtB2, out, 2 * T, 2 * T, D, 256,
        (size_t)T * 2 * T, (size_t)D * 2 * T, (size_t)T * D);
}

// round 8
// speedup vs baseline: 2.0304x; 2.0304x over previous
#include <cuda_runtime.h>
#include <cuda_fp16.h>
#include <cstdint>

#define BATCH 4
#define T 4096
#define D 1024
#define H 64
#define MTOT (BATCH * T)

// ---------------------------------------------------------------------------
// Packed fp16 split streams (K'-contiguous, chunks pre-duplicated):
//   3-term: A chunks [hi|hi|lo], B chunks [hi|lo|hi]
//           => Ahi.Bhi + Ahi.Blo + Alo.Bhi   (~2^-22)  -- QK-proj, scores
//   2-term: A chunks [hi|lo],    B chunks [hi|hi]
//           => (Ahi+Alo).Bhi                  (~2^-12)  -- V-proj
//   1-term: plain fp16 hi                     (~2^-12)  -- P@V (both sides)
// ---------------------------------------------------------------------------
__device__ __align__(256) __half g_xA3[(size_t)MTOT * 3 * D];        // 96 MB
__device__ __align__(256) __half g_xB2[(size_t)MTOT * 2 * D];        // 64 MB
__device__ __align__(256) __half g_wqkB3[128 * 3 * D];               // .75 MB
__device__ __align__(256) __half g_wvA2[(size_t)D * 2 * D];          // 4 MB
__device__ __align__(256) float  g_qk[(size_t)MTOT * 128];           // 8 MB
__device__ __align__(256) __half g_qA3[(size_t)MTOT * 192];          // 6 MB
__device__ __align__(256) __half g_kB3[(size_t)MTOT * 192];          // 6 MB
__device__ __align__(256) float  g_vt[(size_t)D * MTOT];             // 64 MB (V^T fp32)
__device__ __align__(256) __half g_vh[(size_t)BATCH * D * T];        // 32 MB (V^T fp16 hi)
__device__ __align__(256) float  g_S[(size_t)BATCH * T * T];         // 256 MB
__device__ __align__(256) __half g_ph[(size_t)BATCH * T * T];        // 128 MB (P fp16 hi)

// ---------------------------------------------------------------------------
// Pack: split into fp16 hi/lo, chunk-duplicated layout per mode.
// mode 0: [hi|hi|lo] (3A)  mode 1: [hi|lo|hi] (3B)
// mode 2: [hi|lo]    (2A)  mode 3: [hi|hi]    (2B)
// ---------------------------------------------------------------------------
__global__ __launch_bounds__(256)
void packN(const float* __restrict__ src, int ldsrc, int col0, int ncols,
           __half* __restrict__ dst, int mode, float scale, int total) {
    int idx = blockIdx.x * 256 + threadIdx.x;
    if (idx >= total) return;
    int row = idx / ncols;
    int k = idx - row * ncols;
    float v = src[(size_t)row * ldsrc + col0 + k] * scale;
    __half hi = __float2half_rn(v);
    __half lo = __float2half_rn(v - __half2float(hi));
    int c = k >> 6, o = k & 63;
    if (mode <= 1) {
        size_t base = (size_t)row * (3 * ncols) + (size_t)c * 192 + o;
        dst[base] = hi;
        dst[base + 64]  = (mode == 1) ? lo : hi;
        dst[base + 128] = (mode == 1) ? hi : lo;
    } else {
        size_t base = (size_t)row * (2 * ncols) + (size_t)c * 128 + o;
        dst[base] = hi;
        dst[base + 64] = (mode == 3) ? hi : lo;
    }
}

// plain fp16 truncation pack (contiguous, coalesced)
__global__ __launch_bounds__(256)
void packHi(const float* __restrict__ src, int ldsrc, int col0, int ncols,
            __half* __restrict__ dst, int total) {
    int idx = blockIdx.x * 256 + threadIdx.x;
    if (idx >= total) return;
    int row = idx / ncols;
    int k = idx - row * ncols;
    dst[(size_t)row * ncols + k] = __float2half_rn(src[(size_t)row * ldsrc + col0 + k]);
}

// ---------------------------------------------------------------------------
// HMMA fp16 GEMM: C[M,N] = A'[M,K'] * B'[N,K']^T (K'-contiguous streams).
// 128x128x32 CTA tile, 8 warps 4(M)x2(N), warp tile 32x64.
// 2-stage cp.async double buffer (R5-proven structure).
// CAUSAL: skip tiles bx > by.  KLIMIT: nc = KMUL*(by+1).
// ---------------------------------------------------------------------------
#define ASTRIDE 80
#define TILE_BYTES (128 * ASTRIDE)
#define STAGE_BYTES (2 * TILE_BYTES)

__device__ __forceinline__ uint32_t smem_u32(const void* p) {
    uint32_t a;
    asm("{ .reg .u64 t; cvta.to.shared.u64 t, %1; cvt.u32.u64 %0, t; }" : "=r"(a) : "l"(p));
    return a;
}
__device__ __forceinline__ void cp16(uint32_t dst, const void* src) {
    asm volatile("cp.async.cg.shared.global [%0], [%1], 16;" :: "r"(dst), "l"(src));
}
__device__ __forceinline__ void ldm_x4(uint32_t* r, uint32_t addr) {
    asm volatile("ldmatrix.sync.aligned.m8n8.x4.shared.b16 {%0,%1,%2,%3}, [%4];"
                 : "=r"(r[0]), "=r"(r[1]), "=r"(r[2]), "=r"(r[3]) : "r"(addr));
}
__device__ __forceinline__ void mma16816(float* d, const uint32_t* a, const uint32_t* b) {
    asm volatile(
        "mma.sync.aligned.m16n8k16.row.col.f32.f16.f16.f32 "
        "{%0,%1,%2,%3}, {%4,%5,%6,%7}, {%8,%9}, {%0,%1,%2,%3};"
        : "+f"(d[0]), "+f"(d[1]), "+f"(d[2]), "+f"(d[3])
        : "r"(a[0]), "r"(a[1]), "r"(a[2]), "r"(a[3]), "r"(b[0]), "r"(b[1]));
}

template<bool CAUSAL, int KMUL>
__global__ __launch_bounds__(256)
void gemm_hmma(const __half* __restrict__ A, const __half* __restrict__ B,
               float* __restrict__ C, int lda, int ldb, int ldc, int NC,
               size_t sA, size_t sB, size_t sC) {
    const int bx = blockIdx.x, by = blockIdx.y, bz = blockIdx.z;
    if (CAUSAL && bx > by) return;
    A += (size_t)bz * sA;
    B += (size_t)bz * sB;
    C += (size_t)bz * sC;
    const int row0 = by * 128, col0 = bx * 128;
    const int nc = (KMUL > 0) ? min(NC, KMUL * (by + 1)) : NC;

    __shared__ __align__(128) char smem[2 * STAGE_BYTES];
    const uint32_t sbase = smem_u32(smem);

    const int tid = threadIdx.x;
    const int lane = tid & 31;
    const int w = tid >> 5;
    const int wm = (w & 3) * 32;
    const int wn = (w >> 2) * 64;

    const int lr = tid >> 1;
    const int lh = (tid & 1);
    const __half* Ap = A + (size_t)(row0 + lr) * lda + lh * 16;
    const __half* Bp = B + (size_t)(col0 + lr) * ldb + lh * 16;
    const uint32_t dstRow = lr * ASTRIDE + lh * 32;

    uint32_t aoff[2];
#pragma unroll
    for (int mt = 0; mt < 2; mt++)
        aoff[mt] = (uint32_t)((wm + mt * 16 + (lane & 15)) * ASTRIDE + ((lane >> 4) * 16));
    uint32_t boff[4];
#pragma unroll
    for (int nt2 = 0; nt2 < 4; nt2++)
        boff[nt2] = (uint32_t)((wn + nt2 * 16 + (lane & 7) + ((lane >> 4) & 1) * 8) * ASTRIDE
                               + (((lane >> 3) & 1) * 16));

    float acc[2][8][4];
#pragma unroll
    for (int mt = 0; mt < 2; mt++)
#pragma unroll
        for (int nt = 0; nt < 8; nt++)
#pragma unroll
            for (int q = 0; q < 4; q++) acc[mt][nt][q] = 0.f;

    {
        uint32_t ad = sbase + dstRow;
        uint32_t bd = sbase + TILE_BYTES + dstRow;
        cp16(ad, Ap);       cp16(ad + 16, Ap + 8);
        cp16(bd, Bp);       cp16(bd + 16, Bp + 8);
        asm volatile("cp.async.commit_group;" ::: "memory");
    }

    int buf = 0;
    for (int kc = 0; kc < nc; kc++) {
        if (kc + 1 < nc) {
            const __half* a2 = Ap + (size_t)(kc + 1) * 32;
            const __half* b2 = Bp + (size_t)(kc + 1) * 32;
            uint32_t st = sbase + (buf ^ 1) * STAGE_BYTES;
            cp16(st + dstRow, a2);                    cp16(st + dstRow + 16, a2 + 8);
            cp16(st + TILE_BYTES + dstRow, b2);       cp16(st + TILE_BYTES + dstRow + 16, b2 + 8);
            asm volatile("cp.async.commit_group;" ::: "memory");
            asm volatile("cp.async.wait_group 1;" ::: "memory");
        } else {
            asm volatile("cp.async.wait_group 0;" ::: "memory");
        }
        __syncthreads();

        const uint32_t abase = sbase + buf * STAGE_BYTES;
        const uint32_t bbase = abase + TILE_BYTES;
#pragma unroll
        for (int k16 = 0; k16 < 2; k16++) {
            const uint32_t ko = k16 * 32;
            uint32_t afr[2][4];
            ldm_x4(afr[0], abase + aoff[0] + ko);
            ldm_x4(afr[1], abase + aoff[1] + ko);
            uint32_t bfr[8][2];
#pragma unroll
            for (int nt2 = 0; nt2 < 4; nt2++) {
                uint32_t r[4];
                ldm_x4(r, bbase + boff[nt2] + ko);
                bfr[2 * nt2][0] = r[0];     bfr[2 * nt2][1] = r[1];
                bfr[2 * nt2 + 1][0] = r[2]; bfr[2 * nt2 + 1][1] = r[3];
            }
#pragma unroll
            for (int mt = 0; mt < 2; mt++)
#pragma unroll
                for (int nt = 0; nt < 8; nt++)
                    mma16816(acc[mt][nt], afr[mt], bfr[nt]);
        }
        __syncthreads();
        buf ^= 1;
    }

    const int rq = lane >> 2;
    const int cq = (lane & 3) * 2;
#pragma unroll
    for (int mt = 0; mt < 2; mt++) {
#pragma unroll
        for (int nt = 0; nt < 8; nt++) {
            float* p = C + (size_t)(row0 + wm + mt * 16 + rq) * ldc + col0 + wn + nt * 8 + cq;
            p[0] = acc[mt][nt][0];
            p[1] = acc[mt][nt][1];
            float* p2 = p + 8 * (size_t)ldc;
            p2[0] = acc[mt][nt][2];
            p2[1] = acc[mt][nt][3];
        }
    }
}

// ---------------------------------------------------------------------------
// Causal softmax: fp32 scores row -> plain fp16 P row (hi only).
// Writes only cols < tile-aligned causal limit (all the P@V GEMM reads).
// ---------------------------------------------------------------------------
__global__ __launch_bounds__(256)
void softmax_hi(const float* __restrict__ S, __half* __restrict__ P) {
    const int i = blockIdx.x;
    const int b = blockIdx.y;
    const float* row = S + ((size_t)b * T + i) * (size_t)T;
    __half* prow = P + ((size_t)b * T + i) * (size_t)T;
    const int tid = threadIdx.x;
    const int len = i + 1;
    const int jmax = ((i >> 7) + 1) << 7;   // tile-aligned causal limit

    constexpr int R = T / 256;
    float local[R];
    float m = -3.4e38f;
#pragma unroll
    for (int r = 0; r < R; r++) {
        int j = r * 256 + tid;
        float v = (j < len) ? row[j] : -3.4e38f;
        local[r] = v;
        m = fmaxf(m, v);
    }
    __shared__ float red[8];
#pragma unroll
    for (int o = 16; o; o >>= 1) m = fmaxf(m, __shfl_xor_sync(0xffffffffu, m, o));
    if ((tid & 31) == 0) red[tid >> 5] = m;
    __syncthreads();
    m = red[0];
#pragma unroll
    for (int w = 1; w < 8; w++) m = fmaxf(m, red[w]);
    __syncthreads();

    float s = 0.f;
#pragma unroll
    for (int r = 0; r < R; r++) {
        int j = r * 256 + tid;
        float e = (j < len) ? __expf(local[r] - m) : 0.f;
        local[r] = e;
        s += e;
    }
#pragma unroll
    for (int o = 16; o; o >>= 1) s += __shfl_xor_sync(0xffffffffu, s, o);
    if ((tid & 31) == 0) red[tid >> 5] = s;
    __syncthreads();
    s = red[0];
#pragma unroll
    for (int w = 1; w < 8; w++) s += red[w];

    const float inv = 1.f / s;
#pragma unroll
    for (int r = 0; r < R; r++) {
        int j = r * 256 + tid;
        if (j < jmax) prow[j] = __float2half_rn(local[r] * inv);
    }
}

// ---------------------------------------------------------------------------
// kernel_launch
// ---------------------------------------------------------------------------
extern "C" void kernel_launch(void* const* d_in, const int* in_sizes, int n_in,
                              void* d_out, int out_size) {
    const float* x  = (const float*)d_in[0];
    const float* Wk = (const float*)d_in[1];
    const float* Wq = (const float*)d_in[2];
    const float* Wv = (const float*)d_in[3];
    float* out = (float*)d_out;

    __half *xA3, *xB2, *wqkB3, *wvA2, *qA3, *kB3, *vh, *ph;
    float *qk, *vt, *S;
    cudaGetSymbolAddress((void**)&xA3, g_xA3);
    cudaGetSymbolAddress((void**)&xB2, g_xB2);
    cudaGetSymbolAddress((void**)&wqkB3, g_wqkB3);
    cudaGetSymbolAddress((void**)&wvA2, g_wvA2);
    cudaGetSymbolAddress((void**)&qk, g_qk);
    cudaGetSymbolAddress((void**)&qA3, g_qA3);
    cudaGetSymbolAddress((void**)&kB3, g_kB3);
    cudaGetSymbolAddress((void**)&vt, g_vt);
    cudaGetSymbolAddress((void**)&vh, g_vh);
    cudaGetSymbolAddress((void**)&S, g_S);
    cudaGetSymbolAddress((void**)&ph, g_ph);

    // 1) input packs
    packN<<<(MTOT * D + 255) / 256, 256>>>(x, D, 0, D, xA3, 0, 1.f, MTOT * D);   // 3A
    packN<<<(MTOT * D + 255) / 256, 256>>>(x, D, 0, D, xB2, 3, 1.f, MTOT * D);   // 2B
    packN<<<(64 * D + 255) / 256, 256>>>(Wq, D, 0, D, wqkB3, 1, 1.f, 64 * D);    // 3B
    packN<<<(64 * D + 255) / 256, 256>>>(Wk, D, 0, D, wqkB3 + (size_t)64 * 3 * D, 1, 1.f, 64 * D);
    packN<<<(D * D + 255) / 256, 256>>>(Wv, D, 0, D, wvA2, 2, 1.f, D * D);       // 2A

    // 2) QK projection (3-term): xA3 x wqkB3^T -> qk fp32 [16384,128]
    gemm_hmma<false, 0><<<dim3(1, MTOT / 128, 1), 256>>>(
        xA3, wqkB3, qk, 3 * D, 3 * D, 128, 96, 0, 0, 0);

    // 3) V^T projection (2-term): wvA2 x xB2^T -> vt fp32 [1024,16384]
    gemm_hmma<false, 0><<<dim3(MTOT / 128, D / 128, 1), 256>>>(
        wvA2, xB2, vt, 2 * D, 2 * D, MTOT, 64, 0, 0, 0);

    // 4) split-pack Q (pre-scaled 1/8, 3A), K (3B); plain-pack V^T hi per batch
    packN<<<(MTOT * 64 + 255) / 256, 256>>>(qk, 128, 0, 64, qA3, 0, 0.125f, MTOT * 64);
    packN<<<(MTOT * 64 + 255) / 256, 256>>>(qk, 128, 64, 64, kB3, 1, 1.f, MTOT * 64);
    for (int b = 0; b < BATCH; b++) {
        packHi<<<(D * T + 255) / 256, 256>>>(
            vt, MTOT, b * T, T, vh + (size_t)b * D * T, D * T);
    }

    // 5) scores (3-term, causal tile skip): S[b] = Qs K^T
    gemm_hmma<true, 0><<<dim3(T / 128, T / 128, BATCH), 256>>>(
        qA3, kB3, S, 192, 192, T, 6,
        (size_t)T * 192, (size_t)T * 192, (size_t)T * T);

    // 6) softmax -> plain fp16 P (hi only, causal region)
    softmax_hi<<<dim3(T, BATCH), 256>>>(S, ph);

    // 7) out[b] = P[b] @ V[b]: plain fp16 GEMM, causal K-limit (4 chunks/tile-row)
    gemm_hmma<false, 4><<<dim3(D / 128, T / 128, BATCH), 256>>>(
        ph, vh, out, T, T, D, T / 32,
        (size_t)T * T, (size_t)D * T, (size_t)T * D);
}

// round 9
// speedup vs baseline: 2.0670x; 1.0181x over previous
#include <cuda_runtime.h>
#include <cuda_fp16.h>
#include <cstdint>

#define BATCH 4
#define T 4096
#define D 1024
#define H 64
#define MTOT (BATCH * T)

// ---------------------------------------------------------------------------
// Packed fp16 split streams (K'-contiguous, chunks pre-duplicated):
//   3-term: A chunks [hi|hi|lo], B chunks [hi|lo|hi]
//           => Ahi.Bhi + Ahi.Blo + Alo.Bhi   (~2^-22)  -- QK-proj, scores
//   2-term: A chunks [hi|lo],    B chunks [hi|hi]
//           => (Ahi+Alo).Bhi                  (~2^-12)  -- V-proj
//   1-term: plain fp16                        (~2^-12)  -- P@V
// ---------------------------------------------------------------------------
__device__ __align__(256) __half g_xA3[(size_t)MTOT * 3 * D];        // 96 MB
__device__ __align__(256) __half g_xB2[(size_t)MTOT * 2 * D];        // 64 MB
__device__ __align__(256) __half g_wqkB3[128 * 3 * D];               // .75 MB
__device__ __align__(256) __half g_wvA2[(size_t)D * 2 * D];          // 4 MB
__device__ __align__(256) float  g_qkp[(size_t)2 * MTOT * 128];      // 16 MB (split-K partials)
__device__ __align__(256) __half g_qA3[(size_t)MTOT * 192];          // 6 MB
__device__ __align__(256) __half g_kB3[(size_t)MTOT * 192];          // 6 MB
__device__ __align__(256) __half g_vh[(size_t)D * MTOT];             // 32 MB (V^T fp16)
__device__ __align__(256) float  g_S[(size_t)BATCH * T * T];         // 256 MB
__device__ __align__(256) __half g_ph[(size_t)BATCH * T * T];        // 128 MB (P fp16)

// ---------------------------------------------------------------------------
// Fused input pack: x -> xA3 ([hi|hi|lo]) and xB2 ([hi|hi]) in one read
// ---------------------------------------------------------------------------
__global__ __launch_bounds__(256)
void pack_x(const float* __restrict__ x,
            __half* __restrict__ xA3, __half* __restrict__ xB2) {
    int idx = blockIdx.x * 256 + threadIdx.x;
    if (idx >= MTOT * D) return;
    int row = idx >> 10;
    int k = idx & 1023;
    float v = x[idx];
    __half hi = __float2half_rn(v);
    __half lo = __float2half_rn(v - __half2float(hi));
    int c = k >> 6, o = k & 63;
    size_t b3 = (size_t)row * 3072 + (size_t)c * 192 + o;
    xA3[b3] = hi; xA3[b3 + 64] = hi; xA3[b3 + 128] = lo;
    size_t b2 = (size_t)row * 2048 + (size_t)c * 128 + o;
    xB2[b2] = hi; xB2[b2 + 64] = hi;
}

// Weight packs. mode 1: [hi|lo|hi] (3B)   mode 2: [hi|lo] (2A)
__global__ __launch_bounds__(256)
void packN(const float* __restrict__ src, int ncols,
           __half* __restrict__ dst, int mode, int total) {
    int idx = blockIdx.x * 256 + threadIdx.x;
    if (idx >= total) return;
    int row = idx / ncols;
    int k = idx - row * ncols;
    float v = src[(size_t)row * ncols + k];
    __half hi = __float2half_rn(v);
    __half lo = __float2half_rn(v - __half2float(hi));
    int c = k >> 6, o = k & 63;
    if (mode == 1) {
        size_t base = (size_t)row * (3 * ncols) + (size_t)c * 192 + o;
        dst[base] = hi; dst[base + 64] = lo; dst[base + 128] = hi;
    } else {
        size_t base = (size_t)row * (2 * ncols) + (size_t)c * 128 + o;
        dst[base] = hi; dst[base + 64] = lo;
    }
}

// Fused QK pack: sum split-K partials, emit qA3 (cols 0-63, scaled 1/8, [hi|hi|lo])
// and kB3 (cols 64-127, [hi|lo|hi]).
__global__ __launch_bounds__(256)
void pack_qk(const float* __restrict__ qkp,
             __half* __restrict__ qA3, __half* __restrict__ kB3) {
    int idx = blockIdx.x * 256 + threadIdx.x;          // MTOT*128
    if (idx >= MTOT * 128) return;
    int row = idx >> 7;
    int col = idx & 127;
    float v = qkp[idx] + qkp[(size_t)MTOT * 128 + idx];
    if (col < 64) {
        v *= 0.125f;
        __half hi = __float2half_rn(v);
        __half lo = __float2half_rn(v - __half2float(hi));
        size_t base = (size_t)row * 192 + col;
        qA3[base] = hi; qA3[base + 64] = hi; qA3[base + 128] = lo;
    } else {
        int o = col - 64;
        __half hi = __float2half_rn(v);
        __half lo = __float2half_rn(v - __half2float(hi));
        size_t base = (size_t)row * 192 + o;
        kB3[base] = hi; kB3[base + 64] = lo; kB3[base + 128] = hi;
    }
}

// ---------------------------------------------------------------------------
// HMMA fp16 GEMM: C[M,N] = A'[M,K'] * B'[N,K']^T, K consumed in 64-half chunks.
// 128x128x64 CTA iteration, 8 warps 4(M)x2(N), warp tile 32x64.
// 2-stage cp.async double buffer. Templated output type (float / half).
// CAUSAL: skip tiles bx > by.  KMUL>0: nc = min(NC, KMUL*(by+1)).
// ---------------------------------------------------------------------------
#define BSTRIDE 144                         // bytes per 64-half smem row (128B + 16B pad)
#define TILE_BYTES (128 * BSTRIDE)          // 18432
#define STAGE_BYTES (2 * TILE_BYTES)        // 36864
#define GSMEM (2 * STAGE_BYTES)             // 73728

__device__ __forceinline__ uint32_t smem_u32(const void* p) {
    uint32_t a;
    asm("{ .reg .u64 t; cvta.to.shared.u64 t, %1; cvt.u32.u64 %0, t; }" : "=r"(a) : "l"(p));
    return a;
}
__device__ __forceinline__ void cp16(uint32_t dst, const void* src) {
    asm volatile("cp.async.cg.shared.global [%0], [%1], 16;" :: "r"(dst), "l"(src));
}
__device__ __forceinline__ void ldm_x4(uint32_t* r, uint32_t addr) {
    asm volatile("ldmatrix.sync.aligned.m8n8.x4.shared.b16 {%0,%1,%2,%3}, [%4];"
                 : "=r"(r[0]), "=r"(r[1]), "=r"(r[2]), "=r"(r[3]) : "r"(addr));
}
__device__ __forceinline__ void mma16816(float* d, const uint32_t* a, const uint32_t* b) {
    asm volatile(
        "mma.sync.aligned.m16n8k16.row.col.f32.f16.f16.f32 "
        "{%0,%1,%2,%3}, {%4,%5,%6,%7}, {%8,%9}, {%0,%1,%2,%3};"
        : "+f"(d[0]), "+f"(d[1]), "+f"(d[2]), "+f"(d[3])
        : "r"(a[0]), "r"(a[1]), "r"(a[2]), "r"(a[3]), "r"(b[0]), "r"(b[1]));
}

template<typename OutT, bool CAUSAL, int KMUL>
__global__ __launch_bounds__(256)
void gemm_hmma(const __half* __restrict__ A, const __half* __restrict__ B,
               OutT* __restrict__ C, int lda, int ldb, int ldc, int NC,
               size_t sA, size_t sB, size_t sC) {
    const int bx = blockIdx.x, by = blockIdx.y, bz = blockIdx.z;
    if (CAUSAL && bx > by) return;
    A += (size_t)bz * sA;
    B += (size_t)bz * sB;
    C += (size_t)bz * sC;
    const int row0 = by * 128, col0 = bx * 128;
    const int nc = (KMUL > 0) ? min(NC, KMUL * (by + 1)) : NC;

    extern __shared__ __align__(128) char smem[];
    const uint32_t sbase = smem_u32(smem);

    const int tid = threadIdx.x;
    const int lane = tid & 31;
    const int w = tid >> 5;
    const int wm = (w & 3) * 32;
    const int wn = (w >> 2) * 64;

    // cp.async mapping: 2 threads per tile row, each 64B (4 x 16B)
    const int lr = tid >> 1;
    const int lh = (tid & 1);
    const __half* Ap = A + (size_t)(row0 + lr) * lda + lh * 32;
    const __half* Bp = B + (size_t)(col0 + lr) * ldb + lh * 32;
    const uint32_t dstRow = lr * BSTRIDE + lh * 64;

    uint32_t aoff[2];
#pragma unroll
    for (int mt = 0; mt < 2; mt++)
        aoff[mt] = (uint32_t)((wm + mt * 16 + (lane & 15)) * BSTRIDE + ((lane >> 4) * 16));
    uint32_t boff[4];
#pragma unroll
    for (int nt2 = 0; nt2 < 4; nt2++)
        boff[nt2] = (uint32_t)((wn + nt2 * 16 + (lane & 7) + ((lane >> 4) & 1) * 8) * BSTRIDE
                               + (((lane >> 3) & 1) * 16));

    float acc[2][8][4];
#pragma unroll
    for (int mt = 0; mt < 2; mt++)
#pragma unroll
        for (int nt = 0; nt < 8; nt++)
#pragma unroll
            for (int q = 0; q < 4; q++) acc[mt][nt][q] = 0.f;

    // prologue: chunk 0 into stage 0
    {
        uint32_t ad = sbase + dstRow;
        uint32_t bd = sbase + TILE_BYTES + dstRow;
#pragma unroll
        for (int i = 0; i < 4; i++) {
            cp16(ad + i * 16, Ap + i * 8);
            cp16(bd + i * 16, Bp + i * 8);
        }
        asm volatile("cp.async.commit_group;" ::: "memory");
    }

    int buf = 0;
    for (int kc = 0; kc < nc; kc++) {
        if (kc + 1 < nc) {
            const __half* a2 = Ap + (size_t)(kc + 1) * 64;
            const __half* b2 = Bp + (size_t)(kc + 1) * 64;
            uint32_t st = sbase + (buf ^ 1) * STAGE_BYTES;
#pragma unroll
            for (int i = 0; i < 4; i++) {
                cp16(st + dstRow + i * 16, a2 + i * 8);
                cp16(st + TILE_BYTES + dstRow + i * 16, b2 + i * 8);
            }
            asm volatile("cp.async.commit_group;" ::: "memory");
            asm volatile("cp.async.wait_group 1;" ::: "memory");
        } else {
            asm volatile("cp.async.wait_group 0;" ::: "memory");
        }
        __syncthreads();

        const uint32_t abase = sbase + buf * STAGE_BYTES;
        const uint32_t bbase = abase + TILE_BYTES;
#pragma unroll
        for (int k16 = 0; k16 < 4; k16++) {
            const uint32_t ko = k16 * 32;
            uint32_t afr[2][4];
            ldm_x4(afr[0], abase + aoff[0] + ko);
            ldm_x4(afr[1], abase + aoff[1] + ko);
            uint32_t bfr[8][2];
#pragma unroll
            for (int nt2 = 0; nt2 < 4; nt2++) {
                uint32_t r[4];
                ldm_x4(r, bbase + boff[nt2] + ko);
                bfr[2 * nt2][0] = r[0];     bfr[2 * nt2][1] = r[1];
                bfr[2 * nt2 + 1][0] = r[2]; bfr[2 * nt2 + 1][1] = r[3];
            }
#pragma unroll
            for (int mt = 0; mt < 2; mt++)
#pragma unroll
                for (int nt = 0; nt < 8; nt++)
                    mma16816(acc[mt][nt], afr[mt], bfr[nt]);
        }
        __syncthreads();
        buf ^= 1;
    }

    // epilogue
    const int rq = lane >> 2;
    const int cq = (lane & 3) * 2;
#pragma unroll
    for (int mt = 0; mt < 2; mt++) {
#pragma unroll
        for (int nt = 0; nt < 8; nt++) {
            size_t r1 = (size_t)(row0 + wm + mt * 16 + rq) * ldc + col0 + wn + nt * 8 + cq;
            size_t r2 = r1 + 8 * (size_t)ldc;
            if (sizeof(OutT) == 4) {
                float* p = (float*)C;
                p[r1] = acc[mt][nt][0]; p[r1 + 1] = acc[mt][nt][1];
                p[r2] = acc[mt][nt][2]; p[r2 + 1] = acc[mt][nt][3];
            } else {
                __half2* p1 = (__half2*)((__half*)C + r1);
                __half2* p2 = (__half2*)((__half*)C + r2);
                *p1 = __floats2half2_rn(acc[mt][nt][0], acc[mt][nt][1]);
                *p2 = __floats2half2_rn(acc[mt][nt][2], acc[mt][nt][3]);
            }
        }
    }
}

// ---------------------------------------------------------------------------
// Causal softmax: fp32 scores row -> fp16 P row (writes cols < tile-aligned
// causal limit; zeros above the diagonal within the limit).
// ---------------------------------------------------------------------------
__global__ __launch_bounds__(256)
void softmax_hi(const float* __restrict__ S, __half* __restrict__ P) {
    const int i = blockIdx.x;
    const int b = blockIdx.y;
    const float* row = S + ((size_t)b * T + i) * (size_t)T;
    __half* prow = P + ((size_t)b * T + i) * (size_t)T;
    const int tid = threadIdx.x;
    const int len = i + 1;
    const int jmax = ((i >> 7) + 1) << 7;

    constexpr int R = T / 256;
    float local[R];
    float m = -3.4e38f;
#pragma unroll
    for (int r = 0; r < R; r++) {
        int j = r * 256 + tid;
        float v = (j < len) ? row[j] : -3.4e38f;
        local[r] = v;
        m = fmaxf(m, v);
    }
    __shared__ float red[8];
#pragma unroll
    for (int o = 16; o; o >>= 1) m = fmaxf(m, __shfl_xor_sync(0xffffffffu, m, o));
    if ((tid & 31) == 0) red[tid >> 5] = m;
    __syncthreads();
    m = red[0];
#pragma unroll
    for (int w = 1; w < 8; w++) m = fmaxf(m, red[w]);
    __syncthreads();

    float s = 0.f;
#pragma unroll
    for (int r = 0; r < R; r++) {
        int j = r * 256 + tid;
        float e = (j < len) ? __expf(local[r] - m) : 0.f;
        local[r] = e;
        s += e;
    }
#pragma unroll
    for (int o = 16; o; o >>= 1) s += __shfl_xor_sync(0xffffffffu, s, o);
    if ((tid & 31) == 0) red[tid >> 5] = s;
    __syncthreads();
    s = red[0];
#pragma unroll
    for (int w = 1; w < 8; w++) s += red[w];

    const float inv = 1.f / s;
#pragma unroll
    for (int r = 0; r < R; r++) {
        int j = r * 256 + tid;
        if (j < jmax) prow[j] = __float2half_rn(local[r] * inv);
    }
}

// ---------------------------------------------------------------------------
// kernel_launch
// ---------------------------------------------------------------------------
extern "C" void kernel_launch(void* const* d_in, const int* in_sizes, int n_in,
                              void* d_out, int out_size) {
    const float* x  = (const float*)d_in[0];
    const float* Wk = (const float*)d_in[1];
    const float* Wq = (const float*)d_in[2];
    const float* Wv = (const float*)d_in[3];
    float* out = (float*)d_out;

    __half *xA3, *xB2, *wqkB3, *wvA2, *qA3, *kB3, *vh, *ph;
    float *qkp, *S;
    cudaGetSymbolAddress((void**)&xA3, g_xA3);
    cudaGetSymbolAddress((void**)&xB2, g_xB2);
    cudaGetSymbolAddress((void**)&wqkB3, g_wqkB3);
    cudaGetSymbolAddress((void**)&wvA2, g_wvA2);
    cudaGetSymbolAddress((void**)&qkp, g_qkp);
    cudaGetSymbolAddress((void**)&qA3, g_qA3);
    cudaGetSymbolAddress((void**)&kB3, g_kB3);
    cudaGetSymbolAddress((void**)&vh, g_vh);
    cudaGetSymbolAddress((void**)&S, g_S);
    cudaGetSymbolAddress((void**)&ph, g_ph);

    cudaFuncSetAttribute(gemm_hmma<float,  false, 0>, cudaFuncAttributeMaxDynamicSharedMemorySize, GSMEM);
    cudaFuncSetAttribute(gemm_hmma<__half, false, 0>, cudaFuncAttributeMaxDynamicSharedMemorySize, GSMEM);
    cudaFuncSetAttribute(gemm_hmma<float,  true,  0>, cudaFuncAttributeMaxDynamicSharedMemorySize, GSMEM);
    cudaFuncSetAttribute(gemm_hmma<float,  false, 2>, cudaFuncAttributeMaxDynamicSharedMemorySize, GSMEM);

    // 1) input packs
    pack_x<<<(MTOT * D + 255) / 256, 256>>>(x, xA3, xB2);
    packN<<<(64 * D + 255) / 256, 256>>>(Wq, D, wqkB3, 1, 64 * D);
    packN<<<(64 * D + 255) / 256, 256>>>(Wk, D, wqkB3 + (size_t)64 * 3 * D, 1, 64 * D);
    packN<<<(D * D + 255) / 256, 256>>>(Wv, D, wvA2, 2, D * D);

    // 2) QK projection (3-term, split-K=2): xA3 x wqkB3^T -> 2 partial fp32 buffers
    gemm_hmma<float, false, 0><<<dim3(1, MTOT / 128, 2), 256, GSMEM>>>(
        xA3, wqkB3, qkp, 3 * D, 3 * D, 128, 24,
        1536, 1536, (size_t)MTOT * 128);

    // 3) V^T projection (2-term): wvA2 x xB2^T -> vh fp16 [1024, 16384] directly
    gemm_hmma<__half, false, 0><<<dim3(MTOT / 128, D / 128, 1), 256, GSMEM>>>(
        wvA2, xB2, vh, 2 * D, 2 * D, MTOT, 32, 0, 0, 0);

    // 4) fused: sum split-K partials -> qA3 (scaled 1/8) + kB3
    pack_qk<<<(MTOT * 128 + 255) / 256, 256>>>(qkp, qA3, kB3);

    // 5) scores (3-term, causal tile skip): S[b] = Qs K^T
    gemm_hmma<float, true, 0><<<dim3(T / 128, T / 128, BATCH), 256, GSMEM>>>(
        qA3, kB3, S, 192, 192, T, 3,
        (size_t)T * 192, (size_t)T * 192, (size_t)T * T);

    // 6) softmax -> fp16 P (causal region only)
    softmax_hi<<<dim3(T, BATCH), 256>>>(S, ph);

    // 7) out[b] = P[b] @ V[b]: fp16 GEMM, causal K-limit (vh shared across batch
    //    via ldb=MTOT, per-batch column offset sB=T)
    gemm_hmma<float, false, 2><<<dim3(D / 128, T / 128, BATCH), 256, GSMEM>>>(
        ph, vh, out, T, MTOT, D, T / 64,
        (size_t)T * T, (size_t)T, (size_t)T * D);
}

// round 10
// speedup vs baseline: 2.4391x; 1.1800x over previous
#include <cuda_runtime.h>
#include <cuda_fp16.h>
#include <cstdint>

#define BATCH 4
#define T 4096
#define D 1024
#define H 64
#define MTOT (BATCH * T)

// ---------------------------------------------------------------------------
// Packed fp16 split streams (K'-contiguous, chunks pre-duplicated):
//   3-term: A chunks [hi|hi|lo], B chunks [hi|lo|hi]
//           => Ahi.Bhi + Ahi.Blo + Alo.Bhi   (~2^-22)  -- QK-proj, scores
//   1-term: plain fp16                        (~2^-12)  -- V-proj, P@V
// ---------------------------------------------------------------------------
__device__ __align__(256) __half g_xA3[(size_t)MTOT * 3 * D];        // 96 MB
__device__ __align__(256) __half g_xhi[(size_t)MTOT * D];            // 32 MB (x fp16)
__device__ __align__(256) __half g_wqkB3[128 * 3 * D];               // .75 MB
__device__ __align__(256) __half g_wvh[(size_t)D * D];               // 2 MB (Wv fp16)
__device__ __align__(256) float  g_qkp[(size_t)2 * MTOT * 128];      // 16 MB (split-K partials)
__device__ __align__(256) __half g_qA3[(size_t)MTOT * 192];          // 6 MB
__device__ __align__(256) __half g_kB3[(size_t)MTOT * 192];          // 6 MB
__device__ __align__(256) __half g_vh[(size_t)D * MTOT];             // 32 MB (V^T fp16)
__device__ __align__(256) float  g_S[(size_t)BATCH * T * T];         // 256 MB
__device__ __align__(256) __half g_ph[(size_t)BATCH * T * T];        // 128 MB (P fp16)

// ---------------------------------------------------------------------------
// Fused input pack: x -> xA3 ([hi|hi|lo]) and xhi (plain fp16) in one read
// ---------------------------------------------------------------------------
__global__ __launch_bounds__(256)
void pack_x(const float* __restrict__ x,
            __half* __restrict__ xA3, __half* __restrict__ xhi) {
    int idx = blockIdx.x * 256 + threadIdx.x;
    if (idx >= MTOT * D) return;
    int row = idx >> 10;
    int k = idx & 1023;
    float v = x[idx];
    __half hi = __float2half_rn(v);
    __half lo = __float2half_rn(v - __half2float(hi));
    int c = k >> 6, o = k & 63;
    size_t b3 = (size_t)row * 3072 + (size_t)c * 192 + o;
    xA3[b3] = hi; xA3[b3 + 64] = hi; xA3[b3 + 128] = lo;
    xhi[idx] = hi;
}

// 3B weight pack: [hi|lo|hi]
__global__ __launch_bounds__(256)
void packW3B(const float* __restrict__ src, int ncols,
             __half* __restrict__ dst, int total) {
    int idx = blockIdx.x * 256 + threadIdx.x;
    if (idx >= total) return;
    int row = idx / ncols;
    int k = idx - row * ncols;
    float v = src[(size_t)row * ncols + k];
    __half hi = __float2half_rn(v);
    __half lo = __float2half_rn(v - __half2float(hi));
    int c = k >> 6, o = k & 63;
    size_t base = (size_t)row * (3 * ncols) + (size_t)c * 192 + o;
    dst[base] = hi; dst[base + 64] = lo; dst[base + 128] = hi;
}

// plain fp16 truncation pack
__global__ __launch_bounds__(256)
void packHi(const float* __restrict__ src, __half* __restrict__ dst, int total) {
    int idx = blockIdx.x * 256 + threadIdx.x;
    if (idx < total) dst[idx] = __float2half_rn(src[idx]);
}

// Fused QK pack: sum split-K partials, emit qA3 (cols 0-63, scaled 1/8, [hi|hi|lo])
// and kB3 (cols 64-127, [hi|lo|hi]).
__global__ __launch_bounds__(256)
void pack_qk(const float* __restrict__ qkp,
             __half* __restrict__ qA3, __half* __restrict__ kB3) {
    int idx = blockIdx.x * 256 + threadIdx.x;          // MTOT*128
    if (idx >= MTOT * 128) return;
    int row = idx >> 7;
    int col = idx & 127;
    float v = qkp[idx] + qkp[(size_t)MTOT * 128 + idx];
    if (col < 64) {
        v *= 0.125f;
        __half hi = __float2half_rn(v);
        __half lo = __float2half_rn(v - __half2float(hi));
        size_t base = (size_t)row * 192 + col;
        qA3[base] = hi; qA3[base + 64] = hi; qA3[base + 128] = lo;
    } else {
        int o = col - 64;
        __half hi = __float2half_rn(v);
        __half lo = __float2half_rn(v - __half2float(hi));
        size_t base = (size_t)row * 192 + o;
        kB3[base] = hi; kB3[base + 64] = lo; kB3[base + 128] = hi;
    }
}

// ---------------------------------------------------------------------------
// HMMA fp16 GEMM: C[M,N] = A'[M,K'] * B'[N,K']^T, K consumed in 64-half chunks.
// 128x128x64 CTA iteration, 8 warps 4(M)x2(N), warp tile 32x64.
// 2-stage cp.async double buffer. Templated output type (float / half).
// CAUSAL: skip tiles bx > by.  KMUL>0: nc = min(NC, KMUL*(by+1)).
// ---------------------------------------------------------------------------
#define BSTRIDE 144
#define TILE_BYTES (128 * BSTRIDE)
#define STAGE_BYTES (2 * TILE_BYTES)
#define GSMEM (2 * STAGE_BYTES)

__device__ __forceinline__ uint32_t smem_u32(const void* p) {
    uint32_t a;
    asm("{ .reg .u64 t; cvta.to.shared.u64 t, %1; cvt.u32.u64 %0, t; }" : "=r"(a) : "l"(p));
    return a;
}
__device__ __forceinline__ void cp16(uint32_t dst, const void* src) {
    asm volatile("cp.async.cg.shared.global [%0], [%1], 16;" :: "r"(dst), "l"(src));
}
__device__ __forceinline__ void ldm_x4(uint32_t* r, uint32_t addr) {
    asm volatile("ldmatrix.sync.aligned.m8n8.x4.shared.b16 {%0,%1,%2,%3}, [%4];"
                 : "=r"(r[0]), "=r"(r[1]), "=r"(r[2]), "=r"(r[3]) : "r"(addr));
}
__device__ __forceinline__ void mma16816(float* d, const uint32_t* a, const uint32_t* b) {
    asm volatile(
        "mma.sync.aligned.m16n8k16.row.col.f32.f16.f16.f32 "
        "{%0,%1,%2,%3}, {%4,%5,%6,%7}, {%8,%9}, {%0,%1,%2,%3};"
        : "+f"(d[0]), "+f"(d[1]), "+f"(d[2]), "+f"(d[3])
        : "r"(a[0]), "r"(a[1]), "r"(a[2]), "r"(a[3]), "r"(b[0]), "r"(b[1]));
}

template<typename OutT, bool CAUSAL, int KMUL>
__global__ __launch_bounds__(256)
void gemm_hmma(const __half* __restrict__ A, const __half* __restrict__ B,
               OutT* __restrict__ C, int lda, int ldb, int ldc, int NC,
               size_t sA, size_t sB, size_t sC) {
    const int bx = blockIdx.x, by = blockIdx.y, bz = blockIdx.z;
    if (CAUSAL && bx > by) return;
    A += (size_t)bz * sA;
    B += (size_t)bz * sB;
    C += (size_t)bz * sC;
    const int row0 = by * 128, col0 = bx * 128;
    const int nc = (KMUL > 0) ? min(NC, KMUL * (by + 1)) : NC;

    extern __shared__ __align__(128) char smem[];
    const uint32_t sbase = smem_u32(smem);

    const int tid = threadIdx.x;
    const int lane = tid & 31;
    const int w = tid >> 5;
    const int wm = (w & 3) * 32;
    const int wn = (w >> 2) * 64;

    const int lr = tid >> 1;
    const int lh = (tid & 1);
    const __half* Ap = A + (size_t)(row0 + lr) * lda + lh * 32;
    const __half* Bp = B + (size_t)(col0 + lr) * ldb + lh * 32;
    const uint32_t dstRow = lr * BSTRIDE + lh * 64;

    uint32_t aoff[2];
#pragma unroll
    for (int mt = 0; mt < 2; mt++)
        aoff[mt] = (uint32_t)((wm + mt * 16 + (lane & 15)) * BSTRIDE + ((lane >> 4) * 16));
    uint32_t boff[4];
#pragma unroll
    for (int nt2 = 0; nt2 < 4; nt2++)
        boff[nt2] = (uint32_t)((wn + nt2 * 16 + (lane & 7) + ((lane >> 4) & 1) * 8) * BSTRIDE
                               + (((lane >> 3) & 1) * 16));

    float acc[2][8][4];
#pragma unroll
    for (int mt = 0; mt < 2; mt++)
#pragma unroll
        for (int nt = 0; nt < 8; nt++)
#pragma unroll
            for (int q = 0; q < 4; q++) acc[mt][nt][q] = 0.f;

    {
        uint32_t ad = sbase + dstRow;
        uint32_t bd = sbase + TILE_BYTES + dstRow;
#pragma unroll
        for (int i = 0; i < 4; i++) {
            cp16(ad + i * 16, Ap + i * 8);
            cp16(bd + i * 16, Bp + i * 8);
        }
        asm volatile("cp.async.commit_group;" ::: "memory");
    }

    int buf = 0;
    for (int kc = 0; kc < nc; kc++) {
        if (kc + 1 < nc) {
            const __half* a2 = Ap + (size_t)(kc + 1) * 64;
            const __half* b2 = Bp + (size_t)(kc + 1) * 64;
            uint32_t st = sbase + (buf ^ 1) * STAGE_BYTES;
#pragma unroll
            for (int i = 0; i < 4; i++) {
                cp16(st + dstRow + i * 16, a2 + i * 8);
                cp16(st + TILE_BYTES + dstRow + i * 16, b2 + i * 8);
            }
            asm volatile("cp.async.commit_group;" ::: "memory");
            asm volatile("cp.async.wait_group 1;" ::: "memory");
        } else {
            asm volatile("cp.async.wait_group 0;" ::: "memory");
        }
        __syncthreads();

        const uint32_t abase = sbase + buf * STAGE_BYTES;
        const uint32_t bbase = abase + TILE_BYTES;
#pragma unroll
        for (int k16 = 0; k16 < 4; k16++) {
            const uint32_t ko = k16 * 32;
            uint32_t afr[2][4];
            ldm_x4(afr[0], abase + aoff[0] + ko);
            ldm_x4(afr[1], abase + aoff[1] + ko);
            uint32_t bfr[8][2];
#pragma unroll
            for (int nt2 = 0; nt2 < 4; nt2++) {
                uint32_t r[4];
                ldm_x4(r, bbase + boff[nt2] + ko);
                bfr[2 * nt2][0] = r[0];     bfr[2 * nt2][1] = r[1];
                bfr[2 * nt2 + 1][0] = r[2]; bfr[2 * nt2 + 1][1] = r[3];
            }
#pragma unroll
            for (int mt = 0; mt < 2; mt++)
#pragma unroll
                for (int nt = 0; nt < 8; nt++)
                    mma16816(acc[mt][nt], afr[mt], bfr[nt]);
        }
        __syncthreads();
        buf ^= 1;
    }

    const int rq = lane >> 2;
    const int cq = (lane & 3) * 2;
#pragma unroll
    for (int mt = 0; mt < 2; mt++) {
#pragma unroll
        for (int nt = 0; nt < 8; nt++) {
            size_t r1 = (size_t)(row0 + wm + mt * 16 + rq) * ldc + col0 + wn + nt * 8 + cq;
            size_t r2 = r1 + 8 * (size_t)ldc;
            if (sizeof(OutT) == 4) {
                float* p = (float*)C;
                p[r1] = acc[mt][nt][0]; p[r1 + 1] = acc[mt][nt][1];
                p[r2] = acc[mt][nt][2]; p[r2 + 1] = acc[mt][nt][3];
            } else {
                __half2* p1 = (__half2*)((__half*)C + r1);
                __half2* p2 = (__half2*)((__half*)C + r2);
                *p1 = __floats2half2_rn(acc[mt][nt][0], acc[mt][nt][1]);
                *p2 = __floats2half2_rn(acc[mt][nt][2], acc[mt][nt][3]);
            }
        }
    }
}

// ---------------------------------------------------------------------------
// Causal softmax: fp32 scores row -> fp16 P row (cols < tile-aligned limit)
// ---------------------------------------------------------------------------
__global__ __launch_bounds__(256)
void softmax_hi(const float* __restrict__ S, __half* __restrict__ P) {
    const int i = blockIdx.x;
    const int b = blockIdx.y;
    const float* row = S + ((size_t)b * T + i) * (size_t)T;
    __half* prow = P + ((size_t)b * T + i) * (size_t)T;
    const int tid = threadIdx.x;
    const int len = i + 1;
    const int jmax = ((i >> 7) + 1) << 7;

    constexpr int R = T / 256;
    float local[R];
    float m = -3.4e38f;
#pragma unroll
    for (int r = 0; r < R; r++) {
        int j = r * 256 + tid;
        float v = (j < len) ? row[j] : -3.4e38f;
        local[r] = v;
        m = fmaxf(m, v);
    }
    __shared__ float red[8];
#pragma unroll
    for (int o = 16; o; o >>= 1) m = fmaxf(m, __shfl_xor_sync(0xffffffffu, m, o));
    if ((tid & 31) == 0) red[tid >> 5] = m;
    __syncthreads();
    m = red[0];
#pragma unroll
    for (int w = 1; w < 8; w++) m = fmaxf(m, red[w]);
    __syncthreads();

    float s = 0.f;
#pragma unroll
    for (int r = 0; r < R; r++) {
        int j = r * 256 + tid;
        float e = (j < len) ? __expf(local[r] - m) : 0.f;
        local[r] = e;
        s += e;
    }
#pragma unroll
    for (int o = 16; o; o >>= 1) s += __shfl_xor_sync(0xffffffffu, s, o);
    if ((tid & 31) == 0) red[tid >> 5] = s;
    __syncthreads();
    s = red[0];
#pragma unroll
    for (int w = 1; w < 8; w++) s += red[w];

    const float inv = 1.f / s;
#pragma unroll
    for (int r = 0; r < R; r++) {
        int j = r * 256 + tid;
        if (j < jmax) prow[j] = __float2half_rn(local[r] * inv);
    }
}

// ---------------------------------------------------------------------------
// kernel_launch
// ---------------------------------------------------------------------------
extern "C" void kernel_launch(void* const* d_in, const int* in_sizes, int n_in,
                              void* d_out, int out_size) {
    const float* x  = (const float*)d_in[0];
    const float* Wk = (const float*)d_in[1];
    const float* Wq = (const float*)d_in[2];
    const float* Wv = (const float*)d_in[3];
    float* out = (float*)d_out;

    __half *xA3, *xhi, *wqkB3, *wvh, *qA3, *kB3, *vh, *ph;
    float *qkp, *S;
    cudaGetSymbolAddress((void**)&xA3, g_xA3);
    cudaGetSymbolAddress((void**)&xhi, g_xhi);
    cudaGetSymbolAddress((void**)&wqkB3, g_wqkB3);
    cudaGetSymbolAddress((void**)&wvh, g_wvh);
    cudaGetSymbolAddress((void**)&qkp, g_qkp);
    cudaGetSymbolAddress((void**)&qA3, g_qA3);
    cudaGetSymbolAddress((void**)&kB3, g_kB3);
    cudaGetSymbolAddress((void**)&vh, g_vh);
    cudaGetSymbolAddress((void**)&S, g_S);
    cudaGetSymbolAddress((void**)&ph, g_ph);

    cudaFuncSetAttribute(gemm_hmma<float,  false, 0>, cudaFuncAttributeMaxDynamicSharedMemorySize, GSMEM);
    cudaFuncSetAttribute(gemm_hmma<__half, false, 0>, cudaFuncAttributeMaxDynamicSharedMemorySize, GSMEM);
    cudaFuncSetAttribute(gemm_hmma<float,  true,  0>, cudaFuncAttributeMaxDynamicSharedMemorySize, GSMEM);
    cudaFuncSetAttribute(gemm_hmma<float,  false, 2>, cudaFuncAttributeMaxDynamicSharedMemorySize, GSMEM);

    // 1) input packs
    pack_x<<<(MTOT * D + 255) / 256, 256>>>(x, xA3, xhi);
    packW3B<<<(64 * D + 255) / 256, 256>>>(Wq, D, wqkB3, 64 * D);
    packW3B<<<(64 * D + 255) / 256, 256>>>(Wk, D, wqkB3 + (size_t)64 * 3 * D, 64 * D);
    packHi<<<(D * D + 255) / 256, 256>>>(Wv, wvh, D * D);

    // 2) QK projection (3-term, split-K=2): xA3 x wqkB3^T -> 2 partial fp32 buffers
    gemm_hmma<float, false, 0><<<dim3(1, MTOT / 128, 2), 256, GSMEM>>>(
        xA3, wqkB3, qkp, 3 * D, 3 * D, 128, 24,
        1536, 1536, (size_t)MTOT * 128);

    // 3) V^T projection (1-term fp16): wvh[1024,1024] x xhi[16384,1024]^T -> vh
    gemm_hmma<__half, false, 0><<<dim3(MTOT / 128, D / 128, 1), 256, GSMEM>>>(
        wvh, xhi, vh, D, D, MTOT, 16, 0, 0, 0);

    // 4) fused: sum split-K partials -> qA3 (scaled 1/8) + kB3
    pack_qk<<<(MTOT * 128 + 255) / 256, 256>>>(qkp, qA3, kB3);

    // 5) scores (3-term, causal tile skip): S[b] = Qs K^T
    gemm_hmma<float, true, 0><<<dim3(T / 128, T / 128, BATCH), 256, GSMEM>>>(
        qA3, kB3, S, 192, 192, T, 3,
        (size_t)T * 192, (size_t)T * 192, (size_t)T * T);

    // 6) softmax -> fp16 P (causal region only)
    softmax_hi<<<dim3(T, BATCH), 256>>>(S, ph);

    // 7) out[b] = P[b] @ V[b]: fp16 GEMM, causal K-limit
    gemm_hmma<float, false, 2><<<dim3(D / 128, T / 128, BATCH), 256, GSMEM>>>(
        ph, vh, out, T, MTOT, D, T / 64,
        (size_t)T * T, (size_t)T, (size_t)T * D);
}

// round 11
// speedup vs baseline: 2.7345x; 1.1211x over previous
#include <cuda_runtime.h>
#include <cuda_fp16.h>
#include <cstdint>

#define BATCH 4
#define T 4096
#define D 1024
#define H 64
#define MTOT (BATCH * T)

// ---------------------------------------------------------------------------
// fp16 split streams (K'-contiguous):
//   2-term pair: A chunks [hi|lo] x B chunks [hi|hi] => (Ahi+Alo).Bhi (~2^-12 on B)
//   1-term: plain fp16 both sides
// QK-proj: xA2 x wqkB2   scores: qA2 x kB2   V-proj / P@V: plain
// ---------------------------------------------------------------------------
__device__ __align__(256) __half g_xA2[(size_t)MTOT * 2 * D];        // 64 MB
__device__ __align__(256) __half g_xhi[(size_t)MTOT * D];            // 32 MB
__device__ __align__(256) __half g_wqkB2[128 * 2 * D];               // 0.5 MB
__device__ __align__(256) __half g_wvh[(size_t)D * D];               // 2 MB
__device__ __align__(256) float  g_qkp[(size_t)2 * MTOT * 128];      // 16 MB
__device__ __align__(256) __half g_qA2[(size_t)MTOT * 128];          // 4 MB
__device__ __align__(256) __half g_kB2[(size_t)MTOT * 128];          // 4 MB
__device__ __align__(256) __half g_vh[(size_t)D * MTOT];             // 32 MB (V^T)
__device__ __align__(256) float  g_S[(size_t)BATCH * T * T];         // 256 MB
__device__ __align__(256) __half g_ph[(size_t)BATCH * T * T];        // 128 MB

// ---------------------------------------------------------------------------
// Packs
// ---------------------------------------------------------------------------
__global__ __launch_bounds__(256)
void pack_x(const float* __restrict__ x,
            __half* __restrict__ xA2, __half* __restrict__ xhi) {
    int idx = blockIdx.x * 256 + threadIdx.x;
    if (idx >= MTOT * D) return;
    int row = idx >> 10;
    int k = idx & 1023;
    float v = x[idx];
    __half hi = __float2half_rn(v);
    __half lo = __float2half_rn(v - __half2float(hi));
    size_t base = (size_t)row * 2048 + (size_t)(k >> 6) * 128 + (k & 63);
    xA2[base] = hi; xA2[base + 64] = lo;
    xhi[idx] = hi;
}

// W -> [hi|hi] duplicated chunks
__global__ __launch_bounds__(256)
void packW2(const float* __restrict__ src, __half* __restrict__ dst, int total) {
    int idx = blockIdx.x * 256 + threadIdx.x;
    if (idx >= total) return;
    int row = idx >> 10;               // ncols = 1024
    int k = idx & 1023;
    __half hi = __float2half_rn(src[idx]);
    size_t base = (size_t)row * 2048 + (size_t)(k >> 6) * 128 + (k & 63);
    dst[base] = hi; dst[base + 64] = hi;
}

__global__ __launch_bounds__(256)
void packHi(const float* __restrict__ src, __half* __restrict__ dst, int total) {
    int idx = blockIdx.x * 256 + threadIdx.x;
    if (idx < total) dst[idx] = __float2half_rn(src[idx]);
}

// Sum split-K partials; emit qA2 ([hi|lo], scaled 1/8) and kB2 ([hi|hi])
__global__ __launch_bounds__(256)
void pack_qk(const float* __restrict__ qkp,
             __half* __restrict__ qA2, __half* __restrict__ kB2) {
    int idx = blockIdx.x * 256 + threadIdx.x;          // MTOT*128
    if (idx >= MTOT * 128) return;
    int row = idx >> 7;
    int col = idx & 127;
    float v = qkp[idx] + qkp[(size_t)MTOT * 128 + idx];
    if (col < 64) {
        v *= 0.125f;
        __half hi = __float2half_rn(v);
        __half lo = __float2half_rn(v - __half2float(hi));
        size_t base = (size_t)row * 128 + col;
        qA2[base] = hi; qA2[base + 64] = lo;
    } else {
        int o = col - 64;
        __half hi = __float2half_rn(v);
        size_t base = (size_t)row * 128 + o;
        kB2[base] = hi; kB2[base + 64] = hi;
    }
}

// ---------------------------------------------------------------------------
// HMMA fp16 GEMM (R10-proven): 128x128x64 iteration, 8 warps 4x2, 2-stage
// cp.async. Templated OutT. CAUSAL tile skip; KMUL causal K-limit.
// ---------------------------------------------------------------------------
#define BSTRIDE 144
#define TILE_BYTES (128 * BSTRIDE)
#define STAGE_BYTES (2 * TILE_BYTES)
#define GSMEM (2 * STAGE_BYTES)

__device__ __forceinline__ uint32_t smem_u32(const void* p) {
    uint32_t a;
    asm("{ .reg .u64 t; cvta.to.shared.u64 t, %1; cvt.u32.u64 %0, t; }" : "=r"(a) : "l"(p));
    return a;
}
__device__ __forceinline__ void cp16(uint32_t dst, const void* src) {
    asm volatile("cp.async.cg.shared.global [%0], [%1], 16;" :: "r"(dst), "l"(src));
}
__device__ __forceinline__ void ldm_x4(uint32_t* r, uint32_t addr) {
    asm volatile("ldmatrix.sync.aligned.m8n8.x4.shared.b16 {%0,%1,%2,%3}, [%4];"
                 : "=r"(r[0]), "=r"(r[1]), "=r"(r[2]), "=r"(r[3]) : "r"(addr));
}
__device__ __forceinline__ void mma16816(float* d, const uint32_t* a, const uint32_t* b) {
    asm volatile(
        "mma.sync.aligned.m16n8k16.row.col.f32.f16.f16.f32 "
        "{%0,%1,%2,%3}, {%4,%5,%6,%7}, {%8,%9}, {%0,%1,%2,%3};"
        : "+f"(d[0]), "+f"(d[1]), "+f"(d[2]), "+f"(d[3])
        : "r"(a[0]), "r"(a[1]), "r"(a[2]), "r"(a[3]), "r"(b[0]), "r"(b[1]));
}

template<typename OutT, bool CAUSAL, int KMUL>
__global__ __launch_bounds__(256)
void gemm_hmma(const __half* __restrict__ A, const __half* __restrict__ B,
               OutT* __restrict__ C, int lda, int ldb, int ldc, int NC,
               size_t sA, size_t sB, size_t sC) {
    const int bx = blockIdx.x, by = blockIdx.y, bz = blockIdx.z;
    if (CAUSAL && bx > by) return;
    A += (size_t)bz * sA;
    B += (size_t)bz * sB;
    C += (size_t)bz * sC;
    const int row0 = by * 128, col0 = bx * 128;
    const int nc = (KMUL > 0) ? min(NC, KMUL * (by + 1)) : NC;

    extern __shared__ __align__(128) char smem[];
    const uint32_t sbase = smem_u32(smem);

    const int tid = threadIdx.x;
    const int lane = tid & 31;
    const int w = tid >> 5;
    const int wm = (w & 3) * 32;
    const int wn = (w >> 2) * 64;

    const int lr = tid >> 1;
    const int lh = (tid & 1);
    const __half* Ap = A + (size_t)(row0 + lr) * lda + lh * 32;
    const __half* Bp = B + (size_t)(col0 + lr) * ldb + lh * 32;
    const uint32_t dstRow = lr * BSTRIDE + lh * 64;

    uint32_t aoff[2];
#pragma unroll
    for (int mt = 0; mt < 2; mt++)
        aoff[mt] = (uint32_t)((wm + mt * 16 + (lane & 15)) * BSTRIDE + ((lane >> 4) * 16));
    uint32_t boff[4];
#pragma unroll
    for (int nt2 = 0; nt2 < 4; nt2++)
        boff[nt2] = (uint32_t)((wn + nt2 * 16 + (lane & 7) + ((lane >> 4) & 1) * 8) * BSTRIDE
                               + (((lane >> 3) & 1) * 16));

    float acc[2][8][4];
#pragma unroll
    for (int mt = 0; mt < 2; mt++)
#pragma unroll
        for (int nt = 0; nt < 8; nt++)
#pragma unroll
            for (int q = 0; q < 4; q++) acc[mt][nt][q] = 0.f;

    {
        uint32_t ad = sbase + dstRow;
        uint32_t bd = sbase + TILE_BYTES + dstRow;
#pragma unroll
        for (int i = 0; i < 4; i++) {
            cp16(ad + i * 16, Ap + i * 8);
            cp16(bd + i * 16, Bp + i * 8);
        }
        asm volatile("cp.async.commit_group;" ::: "memory");
    }

    int buf = 0;
    for (int kc = 0; kc < nc; kc++) {
        if (kc + 1 < nc) {
            const __half* a2 = Ap + (size_t)(kc + 1) * 64;
            const __half* b2 = Bp + (size_t)(kc + 1) * 64;
            uint32_t st = sbase + (buf ^ 1) * STAGE_BYTES;
#pragma unroll
            for (int i = 0; i < 4; i++) {
                cp16(st + dstRow + i * 16, a2 + i * 8);
                cp16(st + TILE_BYTES + dstRow + i * 16, b2 + i * 8);
            }
            asm volatile("cp.async.commit_group;" ::: "memory");
            asm volatile("cp.async.wait_group 1;" ::: "memory");
        } else {
            asm volatile("cp.async.wait_group 0;" ::: "memory");
        }
        __syncthreads();

        const uint32_t abase = sbase + buf * STAGE_BYTES;
        const uint32_t bbase = abase + TILE_BYTES;
#pragma unroll
        for (int k16 = 0; k16 < 4; k16++) {
            const uint32_t ko = k16 * 32;
            uint32_t afr[2][4];
            ldm_x4(afr[0], abase + aoff[0] + ko);
            ldm_x4(afr[1], abase + aoff[1] + ko);
            uint32_t bfr[8][2];
#pragma unroll
            for (int nt2 = 0; nt2 < 4; nt2++) {
                uint32_t r[4];
                ldm_x4(r, bbase + boff[nt2] + ko);
                bfr[2 * nt2][0] = r[0];     bfr[2 * nt2][1] = r[1];
                bfr[2 * nt2 + 1][0] = r[2]; bfr[2 * nt2 + 1][1] = r[3];
            }
#pragma unroll
            for (int mt = 0; mt < 2; mt++)
#pragma unroll
                for (int nt = 0; nt < 8; nt++)
                    mma16816(acc[mt][nt], afr[mt], bfr[nt]);
        }
        __syncthreads();
        buf ^= 1;
    }

    const int rq = lane >> 2;
    const int cq = (lane & 3) * 2;
#pragma unroll
    for (int mt = 0; mt < 2; mt++) {
#pragma unroll
        for (int nt = 0; nt < 8; nt++) {
            size_t r1 = (size_t)(row0 + wm + mt * 16 + rq) * ldc + col0 + wn + nt * 8 + cq;
            size_t r2 = r1 + 8 * (size_t)ldc;
            if (sizeof(OutT) == 4) {
                float* p = (float*)C;
                p[r1] = acc[mt][nt][0]; p[r1 + 1] = acc[mt][nt][1];
                p[r2] = acc[mt][nt][2]; p[r2 + 1] = acc[mt][nt][3];
            } else {
                __half2* p1 = (__half2*)((__half*)C + r1);
                __half2* p2 = (__half2*)((__half*)C + r2);
                *p1 = __floats2half2_rn(acc[mt][nt][0], acc[mt][nt][1]);
                *p2 = __floats2half2_rn(acc[mt][nt][2], acc[mt][nt][3]);
            }
        }
    }
}

// ---------------------------------------------------------------------------
// Vectorized causal softmax: float4 loads, half2 stores, clipped to jmax.
// thread t handles cols {r*1024 + 4t .. +3}, r = 0..3.
// ---------------------------------------------------------------------------
__global__ __launch_bounds__(256)
void softmax_hi(const float* __restrict__ S, __half* __restrict__ P) {
    const int i = blockIdx.x;
    const int b = blockIdx.y;
    const float* row = S + ((size_t)b * T + i) * (size_t)T;
    __half* prow = P + ((size_t)b * T + i) * (size_t)T;
    const int tid = threadIdx.x;
    const int len = i + 1;
    const int jmax = ((i >> 7) + 1) << 7;

    float4 lv[4];
    float m = -3.4e38f;
#pragma unroll
    for (int r = 0; r < 4; r++) {
        int col = r * 1024 + tid * 4;
        if (col < jmax) {
            float4 v = *(const float4*)(row + col);
            if (col + 0 >= len) v.x = -3.4e38f;
            if (col + 1 >= len) v.y = -3.4e38f;
            if (col + 2 >= len) v.z = -3.4e38f;
            if (col + 3 >= len) v.w = -3.4e38f;
            lv[r] = v;
            m = fmaxf(m, fmaxf(fmaxf(v.x, v.y), fmaxf(v.z, v.w)));
        } else {
            lv[r] = make_float4(-3.4e38f, -3.4e38f, -3.4e38f, -3.4e38f);
        }
    }
    __shared__ float red[8];
#pragma unroll
    for (int o = 16; o; o >>= 1) m = fmaxf(m, __shfl_xor_sync(0xffffffffu, m, o));
    if ((tid & 31) == 0) red[tid >> 5] = m;
    __syncthreads();
    m = red[0];
#pragma unroll
    for (int w = 1; w < 8; w++) m = fmaxf(m, red[w]);
    __syncthreads();

    float s = 0.f;
#pragma unroll
    for (int r = 0; r < 4; r++) {
        int col = r * 1024 + tid * 4;
        if (col < jmax) {
            lv[r].x = __expf(lv[r].x - m);
            lv[r].y = __expf(lv[r].y - m);
            lv[r].z = __expf(lv[r].z - m);
            lv[r].w = __expf(lv[r].w - m);
            s += (lv[r].x + lv[r].y) + (lv[r].z + lv[r].w);
        }
    }
#pragma unroll
    for (int o = 16; o; o >>= 1) s += __shfl_xor_sync(0xffffffffu, s, o);
    if ((tid & 31) == 0) red[tid >> 5] = s;
    __syncthreads();
    s = red[0];
#pragma unroll
    for (int w = 1; w < 8; w++) s += red[w];

    const float inv = 1.f / s;
#pragma unroll
    for (int r = 0; r < 4; r++) {
        int col = r * 1024 + tid * 4;
        if (col < jmax) {
            __half2* p = (__half2*)(prow + col);
            p[0] = __floats2half2_rn(lv[r].x * inv, lv[r].y * inv);
            p[1] = __floats2half2_rn(lv[r].z * inv, lv[r].w * inv);
        }
    }
}

// ---------------------------------------------------------------------------
// kernel_launch: fork V path onto a side stream, join before P@V.
// ---------------------------------------------------------------------------
extern "C" void kernel_launch(void* const* d_in, const int* in_sizes, int n_in,
                              void* d_out, int out_size) {
    const float* x  = (const float*)d_in[0];
    const float* Wk = (const float*)d_in[1];
    const float* Wq = (const float*)d_in[2];
    const float* Wv = (const float*)d_in[3];
    float* out = (float*)d_out;

    static cudaStream_t s2 = nullptr;
    static cudaEvent_t evFork = nullptr, evV = nullptr;
    if (!s2) {
        cudaStreamCreateWithFlags(&s2, cudaStreamNonBlocking);
        cudaEventCreateWithFlags(&evFork, cudaEventDisableTiming);
        cudaEventCreateWithFlags(&evV, cudaEventDisableTiming);
    }

    __half *xA2, *xhi, *wqkB2, *wvh, *qA2, *kB2, *vh, *ph;
    float *qkp, *S;
    cudaGetSymbolAddress((void**)&xA2, g_xA2);
    cudaGetSymbolAddress((void**)&xhi, g_xhi);
    cudaGetSymbolAddress((void**)&wqkB2, g_wqkB2);
    cudaGetSymbolAddress((void**)&wvh, g_wvh);
    cudaGetSymbolAddress((void**)&qkp, g_qkp);
    cudaGetSymbolAddress((void**)&qA2, g_qA2);
    cudaGetSymbolAddress((void**)&kB2, g_kB2);
    cudaGetSymbolAddress((void**)&vh, g_vh);
    cudaGetSymbolAddress((void**)&S, g_S);
    cudaGetSymbolAddress((void**)&ph, g_ph);

    cudaFuncSetAttribute(gemm_hmma<float,  false, 0>, cudaFuncAttributeMaxDynamicSharedMemorySize, GSMEM);
    cudaFuncSetAttribute(gemm_hmma<__half, false, 0>, cudaFuncAttributeMaxDynamicSharedMemorySize, GSMEM);
    cudaFuncSetAttribute(gemm_hmma<float,  true,  0>, cudaFuncAttributeMaxDynamicSharedMemorySize, GSMEM);
    cudaFuncSetAttribute(gemm_hmma<float,  false, 2>, cudaFuncAttributeMaxDynamicSharedMemorySize, GSMEM);

    // ---- legacy stream: weight packs + input pack ----
    packW2<<<(64 * D + 255) / 256, 256>>>(Wq, wqkB2, 64 * D);
    packW2<<<(64 * D + 255) / 256, 256>>>(Wk, wqkB2 + (size_t)64 * 2 * D, 64 * D);
    pack_x<<<(MTOT * D + 255) / 256, 256>>>(x, xA2, xhi);
    cudaEventRecord(evFork, 0);

    // ---- side stream: V path (packHi -> V-proj) ----
    cudaStreamWaitEvent(s2, evFork, 0);
    packHi<<<(D * D + 255) / 256, 256, 0, s2>>>(Wv, wvh, D * D);
    gemm_hmma<__half, false, 0><<<dim3(MTOT / 128, D / 128, 1), 256, GSMEM, s2>>>(
        wvh, xhi, vh, D, D, MTOT, 16, 0, 0, 0);
    cudaEventRecord(evV, s2);

    // ---- legacy stream: QK path ----
    // QK projection (2-term, split-K=2): xA2 x wqkB2^T -> partials
    gemm_hmma<float, false, 0><<<dim3(1, MTOT / 128, 2), 256, GSMEM>>>(
        xA2, wqkB2, qkp, 2 * D, 2 * D, 128, 16,
        1024, 1024, (size_t)MTOT * 128);

    // sum partials -> qA2 (scaled 1/8) + kB2
    pack_qk<<<(MTOT * 128 + 255) / 256, 256>>>(qkp, qA2, kB2);

    // scores (2-term, causal tile skip): S[b] = Qs K^T
    gemm_hmma<float, true, 0><<<dim3(T / 128, T / 128, BATCH), 256, GSMEM>>>(
        qA2, kB2, S, 128, 128, T, 2,
        (size_t)T * 128, (size_t)T * 128, (size_t)T * T);

    // softmax -> fp16 P
    softmax_hi<<<dim3(T, BATCH), 256>>>(S, ph);

    // ---- join: P@V needs vh ----
    cudaStreamWaitEvent(0, evV, 0);
    gemm_hmma<float, false, 2><<<dim3(D / 128, T / 128, BATCH), 256, GSMEM>>>(
        ph, vh, out, T, MTOT, D, T / 64,
        (size_t)T * T, (size_t)T, (size_t)T * D);
}

// round 12
// speedup vs baseline: 2.8231x; 1.0324x over previous
#include <cuda_runtime.h>
#include <cuda_fp16.h>
#include <cstdint>

#define BATCH 4
#define T 4096
#define D 1024
#define H 64
#define MTOT (BATCH * T)

// ---------------------------------------------------------------------------
// fp16 split streams (K'-contiguous):
//   2-term pair: A chunks [hi|lo] x B chunks [hi|hi] => (Ahi+Alo).Bhi
//   1-term: plain fp16 both sides (V-proj, P@V)
// ---------------------------------------------------------------------------
__device__ __align__(256) __half g_xA2[(size_t)MTOT * 2 * D];        // 64 MB
__device__ __align__(256) __half g_xhi[(size_t)MTOT * D];            // 32 MB
__device__ __align__(256) __half g_wqkB2[128 * 2 * D];               // 0.5 MB
__device__ __align__(256) __half g_wvh[(size_t)D * D];               // 2 MB
__device__ __align__(256) __half g_qA2[(size_t)MTOT * 128];          // 4 MB
__device__ __align__(256) __half g_kB2[(size_t)MTOT * 128];          // 4 MB
__device__ __align__(256) __half g_vh[(size_t)D * MTOT];             // 32 MB (V^T)
__device__ __align__(256) float  g_S[(size_t)BATCH * T * T];         // 256 MB
__device__ __align__(256) __half g_ph[(size_t)BATCH * T * T];        // 128 MB

// ---------------------------------------------------------------------------
// Packs
// ---------------------------------------------------------------------------
__global__ __launch_bounds__(256)
void pack_x(const float* __restrict__ x,
            __half* __restrict__ xA2, __half* __restrict__ xhi) {
    int idx = blockIdx.x * 256 + threadIdx.x;
    if (idx >= MTOT * D) return;
    int row = idx >> 10;
    int k = idx & 1023;
    float v = x[idx];
    __half hi = __float2half_rn(v);
    __half lo = __float2half_rn(v - __half2float(hi));
    size_t base = (size_t)row * 2048 + (size_t)(k >> 6) * 128 + (k & 63);
    xA2[base] = hi; xA2[base + 64] = lo;
    xhi[idx] = hi;
}

// Wq+Wk -> [hi|hi] duplicated chunks, single launch (rows 0-63 q, 64-127 k)
__global__ __launch_bounds__(256)
void packW2(const float* __restrict__ Wq, const float* __restrict__ Wk,
            __half* __restrict__ dst) {
    int idx = blockIdx.x * 256 + threadIdx.x;            // 128*1024
    if (idx >= 128 * D) return;
    int row = idx >> 10;
    int k = idx & 1023;
    float v = (row < 64) ? Wq[idx] : Wk[idx - 64 * D];
    __half hi = __float2half_rn(v);
    size_t base = (size_t)row * 2048 + (size_t)(k >> 6) * 128 + (k & 63);
    dst[base] = hi; dst[base + 64] = hi;
}

__global__ __launch_bounds__(256)
void packHi(const float* __restrict__ src, __half* __restrict__ dst, int total) {
    int idx = blockIdx.x * 256 + threadIdx.x;
    if (idx < total) dst[idx] = __float2half_rn(src[idx]);
}

// ---------------------------------------------------------------------------
// HMMA fp16 GEMM: 128x128x64 iteration, 8 warps 4(M)x2(N), 2-stage cp.async.
// QKPACK epilogue writes qA2/kB2 directly (QK projection fusion).
// CAUSAL tile skip; KMUL causal K-limit; byOff = row-tile offset (tail split).
// ---------------------------------------------------------------------------
#define BSTRIDE 144
#define TILE_BYTES (128 * BSTRIDE)
#define STAGE_BYTES (2 * TILE_BYTES)
#define GSMEM (2 * STAGE_BYTES)

__device__ __forceinline__ uint32_t smem_u32(const void* p) {
    uint32_t a;
    asm("{ .reg .u64 t; cvta.to.shared.u64 t, %1; cvt.u32.u64 %0, t; }" : "=r"(a) : "l"(p));
    return a;
}
__device__ __forceinline__ void cp16(uint32_t dst, const void* src) {
    asm volatile("cp.async.cg.shared.global [%0], [%1], 16;" :: "r"(dst), "l"(src));
}
__device__ __forceinline__ void ldm_x4(uint32_t* r, uint32_t addr) {
    asm volatile("ldmatrix.sync.aligned.m8n8.x4.shared.b16 {%0,%1,%2,%3}, [%4];"
                 : "=r"(r[0]), "=r"(r[1]), "=r"(r[2]), "=r"(r[3]) : "r"(addr));
}
__device__ __forceinline__ void mma16816(float* d, const uint32_t* a, const uint32_t* b) {
    asm volatile(
        "mma.sync.aligned.m16n8k16.row.col.f32.f16.f16.f32 "
        "{%0,%1,%2,%3}, {%4,%5,%6,%7}, {%8,%9}, {%0,%1,%2,%3};"
        : "+f"(d[0]), "+f"(d[1]), "+f"(d[2]), "+f"(d[3])
        : "r"(a[0]), "r"(a[1]), "r"(a[2]), "r"(a[3]), "r"(b[0]), "r"(b[1]));
}

__device__ __forceinline__ void qk_store(int row, int c, float v0, float v1) {
    if (c < 64) {
        v0 *= 0.125f; v1 *= 0.125f;
        __half2 hi2 = __floats2half2_rn(v0, v1);
        __half2 lo2 = __floats2half2_rn(v0 - __half2float(__low2half(hi2)),
                                        v1 - __half2float(__high2half(hi2)));
        __half2* q = (__half2*)(g_qA2 + (size_t)row * 128 + c);
        q[0] = hi2; q[32] = lo2;                       // +64 halves
    } else {
        __half2 hi2 = __floats2half2_rn(v0, v1);
        __half2* kk = (__half2*)(g_kB2 + (size_t)row * 128 + (c - 64));
        kk[0] = hi2; kk[32] = hi2;
    }
}

template<typename OutT, bool CAUSAL, int KMUL, bool QKPACK>
__global__ __launch_bounds__(256)
void gemm_hmma(const __half* __restrict__ A, const __half* __restrict__ B,
               OutT* __restrict__ C, int lda, int ldb, int ldc, int NC,
               size_t sA, size_t sB, size_t sC, int byOff) {
    const int bx = blockIdx.x, bz = blockIdx.z;
    const int by = blockIdx.y + byOff;
    if (CAUSAL && bx > by) return;
    A += (size_t)bz * sA;
    B += (size_t)bz * sB;
    C += (size_t)bz * sC;
    const int row0 = by * 128, col0 = bx * 128;
    const int nc = (KMUL > 0) ? min(NC, KMUL * (by + 1)) : NC;

    extern __shared__ __align__(128) char smem[];
    const uint32_t sbase = smem_u32(smem);

    const int tid = threadIdx.x;
    const int lane = tid & 31;
    const int w = tid >> 5;
    const int wm = (w & 3) * 32;
    const int wn = (w >> 2) * 64;

    const int lr = tid >> 1;
    const int lh = (tid & 1);
    const __half* Ap = A + (size_t)(row0 + lr) * lda + lh * 32;
    const __half* Bp = B + (size_t)(col0 + lr) * ldb + lh * 32;
    const uint32_t dstRow = lr * BSTRIDE + lh * 64;

    uint32_t aoff[2];
#pragma unroll
    for (int mt = 0; mt < 2; mt++)
        aoff[mt] = (uint32_t)((wm + mt * 16 + (lane & 15)) * BSTRIDE + ((lane >> 4) * 16));
    uint32_t boff[4];
#pragma unroll
    for (int nt2 = 0; nt2 < 4; nt2++)
        boff[nt2] = (uint32_t)((wn + nt2 * 16 + (lane & 7) + ((lane >> 4) & 1) * 8) * BSTRIDE
                               + (((lane >> 3) & 1) * 16));

    float acc[2][8][4];
#pragma unroll
    for (int mt = 0; mt < 2; mt++)
#pragma unroll
        for (int nt = 0; nt < 8; nt++)
#pragma unroll
            for (int q = 0; q < 4; q++) acc[mt][nt][q] = 0.f;

    {
        uint32_t ad = sbase + dstRow;
        uint32_t bd = sbase + TILE_BYTES + dstRow;
#pragma unroll
        for (int i = 0; i < 4; i++) {
            cp16(ad + i * 16, Ap + i * 8);
            cp16(bd + i * 16, Bp + i * 8);
        }
        asm volatile("cp.async.commit_group;" ::: "memory");
    }

    int buf = 0;
    for (int kc = 0; kc < nc; kc++) {
        if (kc + 1 < nc) {
            const __half* a2 = Ap + (size_t)(kc + 1) * 64;
            const __half* b2 = Bp + (size_t)(kc + 1) * 64;
            uint32_t st = sbase + (buf ^ 1) * STAGE_BYTES;
#pragma unroll
            for (int i = 0; i < 4; i++) {
                cp16(st + dstRow + i * 16, a2 + i * 8);
                cp16(st + TILE_BYTES + dstRow + i * 16, b2 + i * 8);
            }
            asm volatile("cp.async.commit_group;" ::: "memory");
            asm volatile("cp.async.wait_group 1;" ::: "memory");
        } else {
            asm volatile("cp.async.wait_group 0;" ::: "memory");
        }
        __syncthreads();

        const uint32_t abase = sbase + buf * STAGE_BYTES;
        const uint32_t bbase = abase + TILE_BYTES;
#pragma unroll
        for (int k16 = 0; k16 < 4; k16++) {
            const uint32_t ko = k16 * 32;
            uint32_t afr[2][4];
            ldm_x4(afr[0], abase + aoff[0] + ko);
            ldm_x4(afr[1], abase + aoff[1] + ko);
            uint32_t bfr[8][2];
#pragma unroll
            for (int nt2 = 0; nt2 < 4; nt2++) {
                uint32_t r[4];
                ldm_x4(r, bbase + boff[nt2] + ko);
                bfr[2 * nt2][0] = r[0];     bfr[2 * nt2][1] = r[1];
                bfr[2 * nt2 + 1][0] = r[2]; bfr[2 * nt2 + 1][1] = r[3];
            }
#pragma unroll
            for (int mt = 0; mt < 2; mt++)
#pragma unroll
                for (int nt = 0; nt < 8; nt++)
                    mma16816(acc[mt][nt], afr[mt], bfr[nt]);
        }
        __syncthreads();
        buf ^= 1;
    }

    const int rq = lane >> 2;
    const int cq = (lane & 3) * 2;
#pragma unroll
    for (int mt = 0; mt < 2; mt++) {
#pragma unroll
        for (int nt = 0; nt < 8; nt++) {
            const int c = wn + nt * 8 + cq;
            const int rA = row0 + wm + mt * 16 + rq;
            if (QKPACK) {
                qk_store(rA, c, acc[mt][nt][0], acc[mt][nt][1]);
                qk_store(rA + 8, c, acc[mt][nt][2], acc[mt][nt][3]);
            } else {
                size_t r1 = (size_t)rA * ldc + col0 + c;
                size_t r2 = r1 + 8 * (size_t)ldc;
                if (sizeof(OutT) == 4) {
                    float* p = (float*)C;
                    p[r1] = acc[mt][nt][0]; p[r1 + 1] = acc[mt][nt][1];
                    p[r2] = acc[mt][nt][2]; p[r2 + 1] = acc[mt][nt][3];
                } else {
                    *(__half2*)((__half*)C + r1) = __floats2half2_rn(acc[mt][nt][0], acc[mt][nt][1]);
                    *(__half2*)((__half*)C + r2) = __floats2half2_rn(acc[mt][nt][2], acc[mt][nt][3]);
                }
            }
        }
    }
}

// ---------------------------------------------------------------------------
// Vectorized causal softmax (rowOff for tail split)
// ---------------------------------------------------------------------------
__global__ __launch_bounds__(256)
void softmax_hi(const float* __restrict__ S, __half* __restrict__ P, int rowOff) {
    const int i = blockIdx.x + rowOff;
    const int b = blockIdx.y;
    const float* row = S + ((size_t)b * T + i) * (size_t)T;
    __half* prow = P + ((size_t)b * T + i) * (size_t)T;
    const int tid = threadIdx.x;
    const int len = i + 1;
    const int jmax = ((i >> 7) + 1) << 7;

    float4 lv[4];
    float m = -3.4e38f;
#pragma unroll
    for (int r = 0; r < 4; r++) {
        int col = r * 1024 + tid * 4;
        if (col < jmax) {
            float4 v = *(const float4*)(row + col);
            if (col + 0 >= len) v.x = -3.4e38f;
            if (col + 1 >= len) v.y = -3.4e38f;
            if (col + 2 >= len) v.z = -3.4e38f;
            if (col + 3 >= len) v.w = -3.4e38f;
            lv[r] = v;
            m = fmaxf(m, fmaxf(fmaxf(v.x, v.y), fmaxf(v.z, v.w)));
        } else {
            lv[r] = make_float4(-3.4e38f, -3.4e38f, -3.4e38f, -3.4e38f);
        }
    }
    __shared__ float red[8];
#pragma unroll
    for (int o = 16; o; o >>= 1) m = fmaxf(m, __shfl_xor_sync(0xffffffffu, m, o));
    if ((tid & 31) == 0) red[tid >> 5] = m;
    __syncthreads();
    m = red[0];
#pragma unroll
    for (int w = 1; w < 8; w++) m = fmaxf(m, red[w]);
    __syncthreads();

    float s = 0.f;
#pragma unroll
    for (int r = 0; r < 4; r++) {
        int col = r * 1024 + tid * 4;
        if (col < jmax) {
            lv[r].x = __expf(lv[r].x - m);
            lv[r].y = __expf(lv[r].y - m);
            lv[r].z = __expf(lv[r].z - m);
            lv[r].w = __expf(lv[r].w - m);
            s += (lv[r].x + lv[r].y) + (lv[r].z + lv[r].w);
        }
    }
#pragma unroll
    for (int o = 16; o; o >>= 1) s += __shfl_xor_sync(0xffffffffu, s, o);
    if ((tid & 31) == 0) red[tid >> 5] = s;
    __syncthreads();
    s = red[0];
#pragma unroll
    for (int w = 1; w < 8; w++) s += red[w];

    const float inv = 1.f / s;
#pragma unroll
    for (int r = 0; r < 4; r++) {
        int col = r * 1024 + tid * 4;
        if (col < jmax) {
            __half2* p = (__half2*)(prow + col);
            p[0] = __floats2half2_rn(lv[r].x * inv, lv[r].y * inv);
            p[1] = __floats2half2_rn(lv[r].z * inv, lv[r].w * inv);
        }
    }
}

// ---------------------------------------------------------------------------
// kernel_launch: V path on s2; attention tail split into two row-halves
// (legacy stream = heavy half1, s3 = light half0), joined at the end.
// ---------------------------------------------------------------------------
extern "C" void kernel_launch(void* const* d_in, const int* in_sizes, int n_in,
                              void* d_out, int out_size) {
    const float* x  = (const float*)d_in[0];
    const float* Wk = (const float*)d_in[1];
    const float* Wq = (const float*)d_in[2];
    const float* Wv = (const float*)d_in[3];
    float* out = (float*)d_out;

    static cudaStream_t s2 = nullptr, s3 = nullptr;
    static cudaEvent_t evX = nullptr, evV = nullptr, evQK = nullptr, ev3 = nullptr;
    if (!s2) {
        cudaStreamCreateWithFlags(&s2, cudaStreamNonBlocking);
        cudaStreamCreateWithFlags(&s3, cudaStreamNonBlocking);
        cudaEventCreateWithFlags(&evX, cudaEventDisableTiming);
        cudaEventCreateWithFlags(&evV, cudaEventDisableTiming);
        cudaEventCreateWithFlags(&evQK, cudaEventDisableTiming);
        cudaEventCreateWithFlags(&ev3, cudaEventDisableTiming);
    }

    __half *xA2, *xhi, *wqkB2, *wvh, *qA2, *kB2, *vh, *ph;
    float *S;
    cudaGetSymbolAddress((void**)&xA2, g_xA2);
    cudaGetSymbolAddress((void**)&xhi, g_xhi);
    cudaGetSymbolAddress((void**)&wqkB2, g_wqkB2);
    cudaGetSymbolAddress((void**)&wvh, g_wvh);
    cudaGetSymbolAddress((void**)&qA2, g_qA2);
    cudaGetSymbolAddress((void**)&kB2, g_kB2);
    cudaGetSymbolAddress((void**)&vh, g_vh);
    cudaGetSymbolAddress((void**)&S, g_S);
    cudaGetSymbolAddress((void**)&ph, g_ph);

    cudaFuncSetAttribute((const void*)gemm_hmma<float,  false, 0, true >, cudaFuncAttributeMaxDynamicSharedMemorySize, GSMEM);
    cudaFuncSetAttribute((const void*)gemm_hmma<__half, false, 0, false>, cudaFuncAttributeMaxDynamicSharedMemorySize, GSMEM);
    cudaFuncSetAttribute((const void*)gemm_hmma<float,  true,  0, false>, cudaFuncAttributeMaxDynamicSharedMemorySize, GSMEM);
    cudaFuncSetAttribute((const void*)gemm_hmma<float,  false, 2, false>, cudaFuncAttributeMaxDynamicSharedMemorySize, GSMEM);

    // ---- legacy: packs ----
    packW2<<<(128 * D + 255) / 256, 256>>>(Wq, Wk, wqkB2);
    pack_x<<<(MTOT * D + 255) / 256, 256>>>(x, xA2, xhi);
    cudaEventRecord(evX, 0);

    // ---- s2: V path ----
    cudaStreamWaitEvent(s2, evX, 0);
    packHi<<<(D * D + 255) / 256, 256, 0, s2>>>(Wv, wvh, D * D);
    gemm_hmma<__half, false, 0, false><<<dim3(MTOT / 128, D / 128, 1), 256, GSMEM, s2>>>(
        wvh, xhi, vh, D, D, MTOT, 16, 0, 0, 0, 0);
    cudaEventRecord(evV, s2);

    // ---- legacy: fused QK projection (writes qA2 + kB2 directly) ----
    gemm_hmma<float, false, 0, true><<<dim3(1, MTOT / 128, 1), 256, GSMEM>>>(
        xA2, wqkB2, (float*)nullptr, 2 * D, 2 * D, 0, 32, 1024, 1024, 0, 0);
    cudaEventRecord(evQK, 0);

    // ---- s3: light half0 (row tiles 0..15) ----
    cudaStreamWaitEvent(s3, evQK, 0);
    gemm_hmma<float, true, 0, false><<<dim3(16, 16, BATCH), 256, GSMEM, s3>>>(
        qA2, kB2, S, 128, 128, T, 2,
        (size_t)T * 128, (size_t)T * 128, (size_t)T * T, 0);
    softmax_hi<<<dim3(T / 2, BATCH), 256, 0, s3>>>(S, ph, 0);
    cudaStreamWaitEvent(s3, evV, 0);
    gemm_hmma<float, false, 2, false><<<dim3(D / 128, 16, BATCH), 256, GSMEM, s3>>>(
        ph, vh, out, T, MTOT, D, T / 64,
        (size_t)T * T, (size_t)T, (size_t)T * D, 0);
    cudaEventRecord(ev3, s3);

    // ---- legacy: heavy half1 (row tiles 16..31) ----
    gemm_hmma<float, true, 0, false><<<dim3(32, 16, BATCH), 256, GSMEM>>>(
        qA2, kB2, S, 128, 128, T, 2,
        (size_t)T * 128, (size_t)T * 128, (size_t)T * T, 16);
    softmax_hi<<<dim3(T / 2, BATCH), 256>>>(S, ph, T / 2);
    cudaStreamWaitEvent(0, evV, 0);
    gemm_hmma<float, false, 2, false><<<dim3(D / 128, 16, BATCH), 256, GSMEM>>>(
        ph, vh, out, T, MTOT, D, T / 64,
        (size_t)T * T, (size_t)T, (size_t)T * D, 16);

    // ---- join ----
    cudaStreamWaitEvent(0, ev3, 0);
}

// round 14
// speedup vs baseline: 3.5159x; 1.2454x over previous
#include <cuda_runtime.h>
#include <cuda_fp16.h>
#include <cstdint>

#define BATCH 4
#define T 4096
#define D 1024
#define H 64
#define MTOT (BATCH * T)

// ---------------------------------------------------------------------------
// fp16 split streams (K'-contiguous):
//   2-term pair: A chunks [hi|lo] x B chunks [hi|hi] => (Ahi+Alo).Bhi
//   1-term: plain fp16 both sides (V-proj, P@V)
// ---------------------------------------------------------------------------
__device__ __align__(256) __half g_xA2[(size_t)MTOT * 2 * D];        // 64 MB
__device__ __align__(256) __half g_xhi[(size_t)MTOT * D];            // 32 MB
__device__ __align__(256) __half g_wqkB2[128 * 2 * D];               // 0.5 MB
__device__ __align__(256) __half g_wvh[(size_t)D * D];               // 2 MB
__device__ __align__(256) __half g_qA2[(size_t)MTOT * 128];          // 4 MB
__device__ __align__(256) __half g_kB2[(size_t)MTOT * 128];          // 4 MB
__device__ __align__(256) __half g_vh[(size_t)D * MTOT];             // 32 MB (V^T)
__device__ __align__(256) float  g_S[(size_t)BATCH * T * T];         // 256 MB
__device__ __align__(256) __half g_ph[(size_t)BATCH * T * T];        // 128 MB

// ---------------------------------------------------------------------------
// Packs
// ---------------------------------------------------------------------------
__global__ __launch_bounds__(256)
void pack_x(const float* __restrict__ x,
            __half* __restrict__ xA2, __half* __restrict__ xhi) {
    int idx = blockIdx.x * 256 + threadIdx.x;
    if (idx >= MTOT * D) return;
    int row = idx >> 10;
    int k = idx & 1023;
    float v = x[idx];
    __half hi = __float2half_rn(v);
    __half lo = __float2half_rn(v - __half2float(hi));
    size_t base = (size_t)row * 2048 + (size_t)(k >> 6) * 128 + (k & 63);
    xA2[base] = hi; xA2[base + 64] = lo;
    xhi[idx] = hi;
}

__global__ __launch_bounds__(256)
void packW2(const float* __restrict__ Wq, const float* __restrict__ Wk,
            __half* __restrict__ dst) {
    int idx = blockIdx.x * 256 + threadIdx.x;            // 128*1024
    if (idx >= 128 * D) return;
    int row = idx >> 10;
    int k = idx & 1023;
    float v = (row < 64) ? Wq[idx] : Wk[idx - 64 * D];
    __half hi = __float2half_rn(v);
    size_t base = (size_t)row * 2048 + (size_t)(k >> 6) * 128 + (k & 63);
    dst[base] = hi; dst[base + 64] = hi;
}

__global__ __launch_bounds__(256)
void packHi(const float* __restrict__ src, __half* __restrict__ dst, int total) {
    int idx = blockIdx.x * 256 + threadIdx.x;
    if (idx < total) dst[idx] = __float2half_rn(src[idx]);
}

// ---------------------------------------------------------------------------
// HMMA fp16 GEMM: 128x128x64 iteration, 8 warps 4(M)x2(N), 2-stage cp.async.
// Smem: 128B rows with XOR-16B swizzle (chunk ^= row&7) -> 64 KB/CTA, 3 CTA/SM.
// QKPACK epilogue writes qA2/kB2 directly. CAUSAL tile skip; KMUL K-limit;
// byOff = row-tile offset for the attention tail split.
// ---------------------------------------------------------------------------
#define TILE_BYTES (128 * 128)              // 16384
#define STAGE_BYTES (2 * TILE_BYTES)        // 32768
#define GSMEM (2 * STAGE_BYTES)             // 65536

__device__ __forceinline__ uint32_t smem_u32(const void* p) {
    uint32_t a;
    asm("{ .reg .u64 t; cvta.to.shared.u64 t, %1; cvt.u32.u64 %0, t; }" : "=r"(a) : "l"(p));
    return a;
}
__device__ __forceinline__ void cp16(uint32_t dst, const void* src) {
    asm volatile("cp.async.cg.shared.global [%0], [%1], 16;" :: "r"(dst), "l"(src));
}
__device__ __forceinline__ void ldm_x4(uint32_t* r, uint32_t addr) {
    asm volatile("ldmatrix.sync.aligned.m8n8.x4.shared.b16 {%0,%1,%2,%3}, [%4];"
                 : "=r"(r[0]), "=r"(r[1]), "=r"(r[2]), "=r"(r[3]) : "r"(addr));
}
__device__ __forceinline__ void mma16816(float* d, const uint32_t* a, const uint32_t* b) {
    asm volatile(
        "mma.sync.aligned.m16n8k16.row.col.f32.f16.f16.f32 "
        "{%0,%1,%2,%3}, {%4,%5,%6,%7}, {%8,%9}, {%0,%1,%2,%3};"
        : "+f"(d[0]), "+f"(d[1]), "+f"(d[2]), "+f"(d[3])
        : "r"(a[0]), "r"(a[1]), "r"(a[2]), "r"(a[3]), "r"(b[0]), "r"(b[1]));
}

__device__ __forceinline__ void qk_store(int row, int c, float v0, float v1) {
    if (c < 64) {
        v0 *= 0.125f; v1 *= 0.125f;
        __half2 hi2 = __floats2half2_rn(v0, v1);
        __half2 lo2 = __floats2half2_rn(v0 - __half2float(__low2half(hi2)),
                                        v1 - __half2float(__high2half(hi2)));
        __half2* q = (__half2*)(g_qA2 + (size_t)row * 128 + c);
        q[0] = hi2; q[32] = lo2;
    } else {
        __half2 hi2 = __floats2half2_rn(v0, v1);
        __half2* kk = (__half2*)(g_kB2 + (size_t)row * 128 + (c - 64));
        kk[0] = hi2; kk[32] = hi2;
    }
}

template<typename OutT, bool CAUSAL, int KMUL, bool QKPACK>
__global__ __launch_bounds__(256)
void gemm_hmma(const __half* __restrict__ A, const __half* __restrict__ B,
               OutT* __restrict__ C, int lda, int ldb, int ldc, int NC,
               size_t sA, size_t sB, size_t sC, int byOff) {
    const int bx = blockIdx.x, bz = blockIdx.z;
    const int by = blockIdx.y + byOff;
    if (CAUSAL && bx > by) return;
    A += (size_t)bz * sA;
    B += (size_t)bz * sB;
    C += (size_t)bz * sC;
    const int row0 = by * 128, col0 = bx * 128;
    const int nc = (KMUL > 0) ? min(NC, KMUL * (by + 1)) : NC;

    extern __shared__ __align__(128) char smem[];
    const uint32_t sbase = smem_u32(smem);

    const int tid = threadIdx.x;
    const int lane = tid & 31;
    const int w = tid >> 5;
    const int wm = (w & 3) * 32;
    const int wn = (w >> 2) * 64;

    // cp.async mapping: 2 threads per tile row, each 64B = 4 x 16B chunks,
    // chunk index (lh*4+i) XOR-swizzled by row&7.
    const int lr = tid >> 1;
    const int lh = (tid & 1);
    const __half* Ap = A + (size_t)(row0 + lr) * lda + lh * 32;
    const __half* Bp = B + (size_t)(col0 + lr) * ldb + lh * 32;
    const uint32_t dbase = (uint32_t)lr * 128;
    const uint32_t dxr = (uint32_t)(lr & 7);
    uint32_t doff[4];
#pragma unroll
    for (int i = 0; i < 4; i++)
        doff[i] = dbase + ((((uint32_t)(lh * 4 + i)) ^ dxr) << 4);

    // ldmatrix bases: byte row base + row&7 xor key; chunk = 2*k16 + sub
    uint32_t abase[2], axr[2];
#pragma unroll
    for (int mt = 0; mt < 2; mt++) {
        int ar = wm + mt * 16 + (lane & 15);
        abase[mt] = (uint32_t)ar * 128;
        axr[mt] = (uint32_t)(ar & 7);
    }
    const uint32_t ac0 = (uint32_t)(lane >> 4);          // 0/1
    uint32_t bbase2[4], bxr[4];
#pragma unroll
    for (int nt2 = 0; nt2 < 4; nt2++) {
        int br = wn + nt2 * 16 + (lane & 7) + ((lane >> 4) & 1) * 8;
        bbase2[nt2] = (uint32_t)br * 128;
        bxr[nt2] = (uint32_t)(br & 7);
    }
    const uint32_t bc0 = (uint32_t)((lane >> 3) & 1);    // 0/1

    float acc[2][8][4];
#pragma unroll
    for (int mt = 0; mt < 2; mt++)
#pragma unroll
        for (int nt = 0; nt < 8; nt++)
#pragma unroll
            for (int q = 0; q < 4; q++) acc[mt][nt][q] = 0.f;

    // prologue: chunk 0 into stage 0
    {
        uint32_t ad = sbase;
        uint32_t bd = sbase + TILE_BYTES;
#pragma unroll
        for (int i = 0; i < 4; i++) {
            cp16(ad + doff[i], Ap + i * 8);
            cp16(bd + doff[i], Bp + i * 8);
        }
        asm volatile("cp.async.commit_group;" ::: "memory");
    }

    int buf = 0;
    for (int kc = 0; kc < nc; kc++) {
        if (kc + 1 < nc) {
            const __half* a2 = Ap + (size_t)(kc + 1) * 64;
            const __half* b2 = Bp + (size_t)(kc + 1) * 64;
            uint32_t st = sbase + (buf ^ 1) * STAGE_BYTES;
#pragma unroll
            for (int i = 0; i < 4; i++) {
                cp16(st + doff[i], a2 + i * 8);
                cp16(st + TILE_BYTES + doff[i], b2 + i * 8);
            }
            asm volatile("cp.async.commit_group;" ::: "memory");
            asm volatile("cp.async.wait_group 1;" ::: "memory");
        } else {
            asm volatile("cp.async.wait_group 0;" ::: "memory");
        }
        __syncthreads();

        const uint32_t ab = sbase + buf * STAGE_BYTES;
        const uint32_t bb = ab + TILE_BYTES;
#pragma unroll
        for (int k16 = 0; k16 < 4; k16++) {
            uint32_t afr[2][4];
#pragma unroll
            for (int mt = 0; mt < 2; mt++)
                ldm_x4(afr[mt], ab + abase[mt] + ((((uint32_t)(2 * k16) + ac0) ^ axr[mt]) << 4));
            uint32_t bfr[8][2];
#pragma unroll
            for (int nt2 = 0; nt2 < 4; nt2++) {
                uint32_t r[4];
                ldm_x4(r, bb + bbase2[nt2] + ((((uint32_t)(2 * k16) + bc0) ^ bxr[nt2]) << 4));
                bfr[2 * nt2][0] = r[0];     bfr[2 * nt2][1] = r[1];
                bfr[2 * nt2 + 1][0] = r[2]; bfr[2 * nt2 + 1][1] = r[3];
            }
#pragma unroll
            for (int mt = 0; mt < 2; mt++)
#pragma unroll
                for (int nt = 0; nt < 8; nt++)
                    mma16816(acc[mt][nt], afr[mt], bfr[nt]);
        }
        __syncthreads();
        buf ^= 1;
    }

    const int rq = lane >> 2;
    const int cq = (lane & 3) * 2;
#pragma unroll
    for (int mt = 0; mt < 2; mt++) {
#pragma unroll
        for (int nt = 0; nt < 8; nt++) {
            const int c = wn + nt * 8 + cq;
            const int rA = row0 + wm + mt * 16 + rq;
            if (QKPACK) {
                qk_store(rA, c, acc[mt][nt][0], acc[mt][nt][1]);
                qk_store(rA + 8, c, acc[mt][nt][2], acc[mt][nt][3]);
            } else {
                size_t r1 = (size_t)rA * ldc + col0 + c;
                size_t r2 = r1 + 8 * (size_t)ldc;
                if (sizeof(OutT) == 4) {
                    float* p = (float*)C;
                    p[r1] = acc[mt][nt][0]; p[r1 + 1] = acc[mt][nt][1];
                    p[r2] = acc[mt][nt][2]; p[r2 + 1] = acc[mt][nt][3];
                } else {
                    *(__half2*)((__half*)C + r1) = __floats2half2_rn(acc[mt][nt][0], acc[mt][nt][1]);
                    *(__half2*)((__half*)C + r2) = __floats2half2_rn(acc[mt][nt][2], acc[mt][nt][3]);
                }
            }
        }
    }
}

// ---------------------------------------------------------------------------
// Vectorized causal softmax (rowOff for tail split)
// ---------------------------------------------------------------------------
__global__ __launch_bounds__(256)
void softmax_hi(const float* __restrict__ S, __half* __restrict__ P, int rowOff) {
    const int i = blockIdx.x + rowOff;
    const int b = blockIdx.y;
    const float* row = S + ((size_t)b * T + i) * (size_t)T;
    __half* prow = P + ((size_t)b * T + i) * (size_t)T;
    const int tid = threadIdx.x;
    const int len = i + 1;
    const int jmax = ((i >> 7) + 1) << 7;

    float4 lv[4];
    float m = -3.4e38f;
#pragma unroll
    for (int r = 0; r < 4; r++) {
        int col = r * 1024 + tid * 4;
        if (col < jmax) {
            float4 v = *(const float4*)(row + col);
            if (col + 0 >= len) v.x = -3.4e38f;
            if (col + 1 >= len) v.y = -3.4e38f;
            if (col + 2 >= len) v.z = -3.4e38f;
            if (col + 3 >= len) v.w = -3.4e38f;
            lv[r] = v;
            m = fmaxf(m, fmaxf(fmaxf(v.x, v.y), fmaxf(v.z, v.w)));
        } else {
            lv[r] = make_float4(-3.4e38f, -3.4e38f, -3.4e38f, -3.4e38f);
        }
    }
    __shared__ float red[8];
#pragma unroll
    for (int o = 16; o; o >>= 1) m = fmaxf(m, __shfl_xor_sync(0xffffffffu, m, o));
    if ((tid & 31) == 0) red[tid >> 5] = m;
    __syncthreads();
    m = red[0];
#pragma unroll
    for (int w = 1; w < 8; w++) m = fmaxf(m, red[w]);
    __syncthreads();

    float s = 0.f;
#pragma unroll
    for (int r = 0; r < 4; r++) {
        int col = r * 1024 + tid * 4;
        if (col < jmax) {
            lv[r].x = __expf(lv[r].x - m);
            lv[r].y = __expf(lv[r].y - m);
            lv[r].z = __expf(lv[r].z - m);
            lv[r].w = __expf(lv[r].w - m);
            s += (lv[r].x + lv[r].y) + (lv[r].z + lv[r].w);
        }
    }
#pragma unroll
    for (int o = 16; o; o >>= 1) s += __shfl_xor_sync(0xffffffffu, s, o);
    if ((tid & 31) == 0) red[tid >> 5] = s;
    __syncthreads();
    s = red[0];
#pragma unroll
    for (int w = 1; w < 8; w++) s += red[w];

    const float inv = 1.f / s;
#pragma unroll
    for (int r = 0; r < 4; r++) {
        int col = r * 1024 + tid * 4;
        if (col < jmax) {
            __half2* p = (__half2*)(prow + col);
            p[0] = __floats2half2_rn(lv[r].x * inv, lv[r].y * inv);
            p[1] = __floats2half2_rn(lv[r].z * inv, lv[r].w * inv);
        }
    }
}

// ---------------------------------------------------------------------------
// kernel_launch: V path on s2; attention tail split into two row-halves
// (legacy stream = heavy half1, s3 = light half0), joined at the end.
// ---------------------------------------------------------------------------
extern "C" void kernel_launch(void* const* d_in, const int* in_sizes, int n_in,
                              void* d_out, int out_size) {
    const float* x  = (const float*)d_in[0];
    const float* Wk = (const float*)d_in[1];
    const float* Wq = (const float*)d_in[2];
    const float* Wv = (const float*)d_in[3];
    float* out = (float*)d_out;

    static cudaStream_t s2 = nullptr, s3 = nullptr;
    static cudaEvent_t evX = nullptr, evV = nullptr, evQK = nullptr, ev3 = nullptr;
    if (!s2) {
        cudaStreamCreateWithFlags(&s2, cudaStreamNonBlocking);
        cudaStreamCreateWithFlags(&s3, cudaStreamNonBlocking);
        cudaEventCreateWithFlags(&evX, cudaEventDisableTiming);
        cudaEventCreateWithFlags(&evV, cudaEventDisableTiming);
        cudaEventCreateWithFlags(&evQK, cudaEventDisableTiming);
        cudaEventCreateWithFlags(&ev3, cudaEventDisableTiming);
    }

    __half *xA2, *xhi, *wqkB2, *wvh, *qA2, *kB2, *vh, *ph;
    float *S;
    cudaGetSymbolAddress((void**)&xA2, g_xA2);
    cudaGetSymbolAddress((void**)&xhi, g_xhi);
    cudaGetSymbolAddress((void**)&wqkB2, g_wqkB2);
    cudaGetSymbolAddress((void**)&wvh, g_wvh);
    cudaGetSymbolAddress((void**)&qA2, g_qA2);
    cudaGetSymbolAddress((void**)&kB2, g_kB2);
    cudaGetSymbolAddress((void**)&vh, g_vh);
    cudaGetSymbolAddress((void**)&S, g_S);
    cudaGetSymbolAddress((void**)&ph, g_ph);

    cudaFuncSetAttribute((const void*)gemm_hmma<float,  false, 0, true >, cudaFuncAttributeMaxDynamicSharedMemorySize, GSMEM);
    cudaFuncSetAttribute((const void*)gemm_hmma<__half, false, 0, false>, cudaFuncAttributeMaxDynamicSharedMemorySize, GSMEM);
    cudaFuncSetAttribute((const void*)gemm_hmma<float,  true,  0, false>, cudaFuncAttributeMaxDynamicSharedMemorySize, GSMEM);
    cudaFuncSetAttribute((const void*)gemm_hmma<float,  false, 2, false>, cudaFuncAttributeMaxDynamicSharedMemorySize, GSMEM);

    // ---- legacy: packs ----
    packW2<<<(128 * D + 255) / 256, 256>>>(Wq, Wk, wqkB2);
    pack_x<<<(MTOT * D + 255) / 256, 256>>>(x, xA2, xhi);
    cudaEventRecord(evX, 0);

    // ---- s2: V path ----
    cudaStreamWaitEvent(s2, evX, 0);
    packHi<<<(D * D + 255) / 256, 256, 0, s2>>>(Wv, wvh, D * D);
    gemm_hmma<__half, false, 0, false><<<dim3(MTOT / 128, D / 128, 1), 256, GSMEM, s2>>>(
        wvh, xhi, vh, D, D, MTOT, 16, 0, 0, 0, 0);
    cudaEventRecord(evV, s2);

    // ---- legacy: fused QK projection (writes qA2 + kB2 directly) ----
    gemm_hmma<float, false, 0, true><<<dim3(1, MTOT / 128, 1), 256, GSMEM>>>(
        xA2, wqkB2, (float*)nullptr, 2 * D, 2 * D, 0, 32, 1024, 1024, 0, 0);
    cudaEventRecord(evQK, 0);

    // ---- s3: light half0 (row tiles 0..15) ----
    cudaStreamWaitEvent(s3, evQK, 0);
    gemm_hmma<float, true, 0, false><<<dim3(16, 16, BATCH), 256, GSMEM, s3>>>(
        qA2, kB2, S, 128, 128, T, 2,
        (size_t)T * 128, (size_t)T * 128, (size_t)T * T, 0);
    softmax_hi<<<dim3(T / 2, BATCH), 256, 0, s3>>>(S, ph, 0);
    cudaStreamWaitEvent(s3, evV, 0);
    gemm_hmma<float, false, 2, false><<<dim3(D / 128, 16, BATCH), 256, GSMEM, s3>>>(
        ph, vh, out, T, MTOT, D, T / 64,
        (size_t)T * T, (size_t)T, (size_t)T * D, 0);
    cudaEventRecord(ev3, s3);

    // ---- legacy: heavy half1 (row tiles 16..31) ----
    gemm_hmma<float, true, 0, false><<<dim3(32, 16, BATCH), 256, GSMEM>>>(
        qA2, kB2, S, 128, 128, T, 2,
        (size_t)T * 128, (size_t)T * 128, (size_t)T * T, 16);
    softmax_hi<<<dim3(T / 2, BATCH), 256>>>(S, ph, T / 2);
    cudaStreamWaitEvent(0, evV, 0);
    gemm_hmma<float, false, 2, false><<<dim3(D / 128, 16, BATCH), 256, GSMEM>>>(
        ph, vh, out, T, MTOT, D, T / 64,
        (size_t)T * T, (size_t)T, (size_t)T * D, 16);

    // ---- join ----
    cudaStreamWaitEvent(0, ev3, 0);
}

// round 15
// speedup vs baseline: 3.5182x; 1.0007x over previous
#include <cuda_runtime.h>
#include <cuda_fp16.h>
#include <cstdint>

#define BATCH 4
#define T 4096
#define D 1024
#define H 64
#define MTOT (BATCH * T)

// ---------------------------------------------------------------------------
// fp16 split streams: 2-term pair (A [hi|lo] x B [hi|hi]) for QK-proj/scores;
// plain fp16 for V-proj and P@V. S is never materialized: scores run twice
// (max pass, exp pass) with softmax fused into the epilogue.
// ---------------------------------------------------------------------------
__device__ __align__(256) __half g_xA2[(size_t)MTOT * 2 * D];        // 64 MB
__device__ __align__(256) __half g_xhi[(size_t)MTOT * D];            // 32 MB
__device__ __align__(256) __half g_wqkB2[128 * 2 * D];               // 0.5 MB
__device__ __align__(256) __half g_wvh[(size_t)D * D];               // 2 MB
__device__ __align__(256) __half g_qA2[(size_t)MTOT * 128];          // 4 MB
__device__ __align__(256) __half g_kB2[(size_t)MTOT * 128];          // 4 MB
__device__ __align__(256) __half g_vh[(size_t)D * MTOT];             // 32 MB (V^T)
__device__ __align__(256) __half g_ph[(size_t)BATCH * T * T];        // 128 MB (unnorm P)
__device__ __align__(256) float  g_maxpart[(size_t)BATCH * T * 32];  // 8 MB
__device__ __align__(256) float  g_sumpart[(size_t)BATCH * T * 32];  // 8 MB
__device__ __align__(256) float  g_rowmax[(size_t)BATCH * T];        // 64 KB
__device__ __align__(256) float  g_rowinv[(size_t)BATCH * T];        // 64 KB

// ---------------------------------------------------------------------------
// Packs
// ---------------------------------------------------------------------------
__global__ __launch_bounds__(256)
void pack_x(const float* __restrict__ x,
            __half* __restrict__ xA2, __half* __restrict__ xhi) {
    int idx = blockIdx.x * 256 + threadIdx.x;
    if (idx >= MTOT * D) return;
    int row = idx >> 10;
    int k = idx & 1023;
    float v = x[idx];
    __half hi = __float2half_rn(v);
    __half lo = __float2half_rn(v - __half2float(hi));
    size_t base = (size_t)row * 2048 + (size_t)(k >> 6) * 128 + (k & 63);
    xA2[base] = hi; xA2[base + 64] = lo;
    xhi[idx] = hi;
}

__global__ __launch_bounds__(256)
void packW2(const float* __restrict__ Wq, const float* __restrict__ Wk,
            __half* __restrict__ dst) {
    int idx = blockIdx.x * 256 + threadIdx.x;            // 128*1024
    if (idx >= 128 * D) return;
    int row = idx >> 10;
    int k = idx & 1023;
    float v = (row < 64) ? Wq[idx] : Wk[idx - 64 * D];
    __half hi = __float2half_rn(v);
    size_t base = (size_t)row * 2048 + (size_t)(k >> 6) * 128 + (k & 63);
    dst[base] = hi; dst[base + 64] = hi;
}

__global__ __launch_bounds__(256)
void packHi(const float* __restrict__ src, __half* __restrict__ dst, int total) {
    int idx = blockIdx.x * 256 + threadIdx.x;
    if (idx < total) dst[idx] = __float2half_rn(src[idx]);
}

// ---------------------------------------------------------------------------
// Row reduce over causal tiles: doInv=0 -> max, doInv=1 -> 1/sum. Half rows.
// ---------------------------------------------------------------------------
__global__ __launch_bounds__(256)
void reduce_rows(const float* __restrict__ part, float* __restrict__ outv,
                 int rowOff, int doInv) {
    int idx = blockIdx.x * 256 + threadIdx.x;            // BATCH * T/2
    if (idx >= BATCH * (T / 2)) return;
    int b = idx / (T / 2);
    int row = rowOff + (idx % (T / 2));
    int nt = (row >> 7) + 1;
    const float* p = part + ((size_t)b * T + row) * 32;
    if (doInv) {
        float s = 0.f;
        for (int t = 0; t < nt; t++) s += p[t];
        outv[(size_t)b * T + row] = 1.f / s;
    } else {
        float m = -3.4e38f;
        for (int t = 0; t < nt; t++) m = fmaxf(m, p[t]);
        outv[(size_t)b * T + row] = m;
    }
}

// ---------------------------------------------------------------------------
// HMMA fp16 GEMM: 128x128x64 iteration, 8 warps 4(M)x2(N), 2-stage cp.async,
// XOR-16B swizzled smem (64 KB/CTA). MODE selects the epilogue:
//   0 = float C store          1 = half C store
//   2 = QK pack (qA2/kB2)      3 = scores pass1: row-max partials
//   4 = scores pass2: P=exp(s-max) fp16 + row-sum partials
//   5 = P@V with per-row 1/sum scaling
// ---------------------------------------------------------------------------
#define TILE_BYTES (128 * 128)
#define STAGE_BYTES (2 * TILE_BYTES)
#define GSMEM (2 * STAGE_BYTES)             // 65536

__device__ __forceinline__ uint32_t smem_u32(const void* p) {
    uint32_t a;
    asm("{ .reg .u64 t; cvta.to.shared.u64 t, %1; cvt.u32.u64 %0, t; }" : "=r"(a) : "l"(p));
    return a;
}
__device__ __forceinline__ void cp16(uint32_t dst, const void* src) {
    asm volatile("cp.async.cg.shared.global [%0], [%1], 16;" :: "r"(dst), "l"(src));
}
__device__ __forceinline__ void ldm_x4(uint32_t* r, uint32_t addr) {
    asm volatile("ldmatrix.sync.aligned.m8n8.x4.shared.b16 {%0,%1,%2,%3}, [%4];"
                 : "=r"(r[0]), "=r"(r[1]), "=r"(r[2]), "=r"(r[3]) : "r"(addr));
}
__device__ __forceinline__ void mma16816(float* d, const uint32_t* a, const uint32_t* b) {
    asm volatile(
        "mma.sync.aligned.m16n8k16.row.col.f32.f16.f16.f32 "
        "{%0,%1,%2,%3}, {%4,%5,%6,%7}, {%8,%9}, {%0,%1,%2,%3};"
        : "+f"(d[0]), "+f"(d[1]), "+f"(d[2]), "+f"(d[3])
        : "r"(a[0]), "r"(a[1]), "r"(a[2]), "r"(a[3]), "r"(b[0]), "r"(b[1]));
}

__device__ __forceinline__ void qk_store(int row, int c, float v0, float v1) {
    if (c < 64) {
        v0 *= 0.125f; v1 *= 0.125f;
        __half2 hi2 = __floats2half2_rn(v0, v1);
        __half2 lo2 = __floats2half2_rn(v0 - __half2float(__low2half(hi2)),
                                        v1 - __half2float(__high2half(hi2)));
        __half2* q = (__half2*)(g_qA2 + (size_t)row * 128 + c);
        q[0] = hi2; q[32] = lo2;
    } else {
        __half2 hi2 = __floats2half2_rn(v0, v1);
        __half2* kk = (__half2*)(g_kB2 + (size_t)row * 128 + (c - 64));
        kk[0] = hi2; kk[32] = hi2;
    }
}

template<int MODE, bool CAUSAL, int KMUL>
__global__ __launch_bounds__(256)
void gemm_hmma(const __half* __restrict__ A, const __half* __restrict__ B,
               void* __restrict__ Cv, int lda, int ldb, int ldc, int NC,
               size_t sA, size_t sB, size_t sC, int byOff,
               const float* __restrict__ aux, float* __restrict__ auxout) {
    const int bx = blockIdx.x, bz = blockIdx.z;
    const int by = blockIdx.y + byOff;
    if (CAUSAL && bx > by) return;
    A += (size_t)bz * sA;
    B += (size_t)bz * sB;
    const int row0 = by * 128, col0 = bx * 128;
    const int nc = (KMUL > 0) ? min(NC, KMUL * (by + 1)) : NC;

    extern __shared__ __align__(128) char smem[];
    const uint32_t sbase = smem_u32(smem);

    const int tid = threadIdx.x;
    const int lane = tid & 31;
    const int w = tid >> 5;
    const int wm = (w & 3) * 32;
    const int wn = (w >> 2) * 64;

    const int lr = tid >> 1;
    const int lh = (tid & 1);
    const __half* Ap = A + (size_t)(row0 + lr) * lda + lh * 32;
    const __half* Bp = B + (size_t)(col0 + lr) * ldb + lh * 32;
    const uint32_t dbase = (uint32_t)lr * 128;
    const uint32_t dxr = (uint32_t)(lr & 7);
    uint32_t doff[4];
#pragma unroll
    for (int i = 0; i < 4; i++)
        doff[i] = dbase + ((((uint32_t)(lh * 4 + i)) ^ dxr) << 4);

    uint32_t abase[2], axr[2];
#pragma unroll
    for (int mt = 0; mt < 2; mt++) {
        int ar = wm + mt * 16 + (lane & 15);
        abase[mt] = (uint32_t)ar * 128;
        axr[mt] = (uint32_t)(ar & 7);
    }
    const uint32_t ac0 = (uint32_t)(lane >> 4);
    uint32_t bbase2[4], bxr[4];
#pragma unroll
    for (int nt2 = 0; nt2 < 4; nt2++) {
        int br = wn + nt2 * 16 + (lane & 7) + ((lane >> 4) & 1) * 8;
        bbase2[nt2] = (uint32_t)br * 128;
        bxr[nt2] = (uint32_t)(br & 7);
    }
    const uint32_t bc0 = (uint32_t)((lane >> 3) & 1);

    float acc[2][8][4];
#pragma unroll
    for (int mt = 0; mt < 2; mt++)
#pragma unroll
        for (int nt = 0; nt < 8; nt++)
#pragma unroll
            for (int q = 0; q < 4; q++) acc[mt][nt][q] = 0.f;

    {
        uint32_t ad = sbase;
        uint32_t bd = sbase + TILE_BYTES;
#pragma unroll
        for (int i = 0; i < 4; i++) {
            cp16(ad + doff[i], Ap + i * 8);
            cp16(bd + doff[i], Bp + i * 8);
        }
        asm volatile("cp.async.commit_group;" ::: "memory");
    }

    int buf = 0;
    for (int kc = 0; kc < nc; kc++) {
        if (kc + 1 < nc) {
            const __half* a2 = Ap + (size_t)(kc + 1) * 64;
            const __half* b2 = Bp + (size_t)(kc + 1) * 64;
            uint32_t st = sbase + (buf ^ 1) * STAGE_BYTES;
#pragma unroll
            for (int i = 0; i < 4; i++) {
                cp16(st + doff[i], a2 + i * 8);
                cp16(st + TILE_BYTES + doff[i], b2 + i * 8);
            }
            asm volatile("cp.async.commit_group;" ::: "memory");
            asm volatile("cp.async.wait_group 1;" ::: "memory");
        } else {
            asm volatile("cp.async.wait_group 0;" ::: "memory");
        }
        __syncthreads();

        const uint32_t ab = sbase + buf * STAGE_BYTES;
        const uint32_t bb = ab + TILE_BYTES;
#pragma unroll
        for (int k16 = 0; k16 < 4; k16++) {
            uint32_t afr[2][4];
#pragma unroll
            for (int mt = 0; mt < 2; mt++)
                ldm_x4(afr[mt], ab + abase[mt] + ((((uint32_t)(2 * k16) + ac0) ^ axr[mt]) << 4));
            uint32_t bfr[8][2];
#pragma unroll
            for (int nt2 = 0; nt2 < 4; nt2++) {
                uint32_t r[4];
                ldm_x4(r, bb + bbase2[nt2] + ((((uint32_t)(2 * k16) + bc0) ^ bxr[nt2]) << 4));
                bfr[2 * nt2][0] = r[0];     bfr[2 * nt2][1] = r[1];
                bfr[2 * nt2 + 1][0] = r[2]; bfr[2 * nt2 + 1][1] = r[3];
            }
#pragma unroll
            for (int mt = 0; mt < 2; mt++)
#pragma unroll
                for (int nt = 0; nt < 8; nt++)
                    mma16816(acc[mt][nt], afr[mt], bfr[nt]);
        }
        __syncthreads();
        buf ^= 1;
    }

    // ---------------- epilogues ----------------
    const int rq = lane >> 2;
    const int cq = (lane & 3) * 2;

    if (MODE == 3 || MODE == 4) {
        // fused softmax passes: per-row masked max (3) or exp+sum (4)
        float* smf = (float*)smem;
        __half* C = (__half*)Cv + (MODE == 4 ? (size_t)bz * sC : 0);
        float rowred[2][2], rm[2][2];
#pragma unroll
        for (int mt = 0; mt < 2; mt++)
#pragma unroll
            for (int h = 0; h < 2; h++) {
                rowred[mt][h] = (MODE == 3) ? -3.4e38f : 0.f;
                if (MODE == 4)
                    rm[mt][h] = aux[(size_t)bz * T + row0 + wm + mt * 16 + rq + 8 * h];
            }
#pragma unroll
        for (int mt = 0; mt < 2; mt++)
#pragma unroll
            for (int nt = 0; nt < 8; nt++) {
                const int cG = col0 + wn + nt * 8 + cq;
#pragma unroll
                for (int h = 0; h < 2; h++) {
                    const int rG = row0 + wm + mt * 16 + rq + 8 * h;
                    float v0 = acc[mt][nt][2 * h], v1 = acc[mt][nt][2 * h + 1];
                    bool m0 = cG > rG, m1 = cG + 1 > rG;
                    if (MODE == 3) {
                        if (!m0) rowred[mt][h] = fmaxf(rowred[mt][h], v0);
                        if (!m1) rowred[mt][h] = fmaxf(rowred[mt][h], v1);
                    } else {
                        float e0 = m0 ? 0.f : __expf(v0 - rm[mt][h]);
                        float e1 = m1 ? 0.f : __expf(v1 - rm[mt][h]);
                        rowred[mt][h] += e0 + e1;
                        *(__half2*)(C + (size_t)rG * ldc + cG) = __floats2half2_rn(e0, e1);
                    }
                }
            }
#pragma unroll
        for (int mt = 0; mt < 2; mt++)
#pragma unroll
            for (int h = 0; h < 2; h++) {
                float v = rowred[mt][h];
#pragma unroll
                for (int o = 1; o < 4; o <<= 1) {
                    float u = __shfl_xor_sync(0xffffffffu, v, o);
                    v = (MODE == 3) ? fmaxf(v, u) : v + u;
                }
                rowred[mt][h] = v;
            }
        __syncthreads();
        if ((lane & 3) == 0) {
#pragma unroll
            for (int mt = 0; mt < 2; mt++)
#pragma unroll
                for (int h = 0; h < 2; h++)
                    smf[(wm + mt * 16 + rq + 8 * h) * 2 + (w >> 2)] = rowred[mt][h];
        }
        __syncthreads();
        if (tid < 128) {
            float a = smf[tid * 2], b2 = smf[tid * 2 + 1];
            float v = (MODE == 3) ? fmaxf(a, b2) : a + b2;
            auxout[((size_t)bz * T + row0 + tid) * 32 + bx] = v;
        }
        return;
    }

#pragma unroll
    for (int mt = 0; mt < 2; mt++) {
#pragma unroll
        for (int nt = 0; nt < 8; nt++) {
            const int c = wn + nt * 8 + cq;
            const int rA = row0 + wm + mt * 16 + rq;
            if (MODE == 2) {
                qk_store(rA, c, acc[mt][nt][0], acc[mt][nt][1]);
                qk_store(rA + 8, c, acc[mt][nt][2], acc[mt][nt][3]);
            } else if (MODE == 0 || MODE == 5) {
                float* p = (float*)Cv + (size_t)bz * sC;
                float s0 = 1.f, s1 = 1.f;
                if (MODE == 5) {
                    s0 = aux[(size_t)bz * T + rA];
                    s1 = aux[(size_t)bz * T + rA + 8];
                }
                size_t r1 = (size_t)rA * ldc + col0 + c;
                size_t r2 = r1 + 8 * (size_t)ldc;
                p[r1] = acc[mt][nt][0] * s0; p[r1 + 1] = acc[mt][nt][1] * s0;
                p[r2] = acc[mt][nt][2] * s1; p[r2 + 1] = acc[mt][nt][3] * s1;
            } else {  // MODE 1: half store
                __half* p = (__half*)Cv + (size_t)bz * sC;
                size_t r1 = (size_t)rA * ldc + col0 + c;
                size_t r2 = r1 + 8 * (size_t)ldc;
                *(__half2*)(p + r1) = __floats2half2_rn(acc[mt][nt][0], acc[mt][nt][1]);
                *(__half2*)(p + r2) = __floats2half2_rn(acc[mt][nt][2], acc[mt][nt][3]);
            }
        }
    }
}

// ---------------------------------------------------------------------------
// kernel_launch: V path on s2; attention tail split into two row-halves
// (legacy = heavy half1, s3 = light half0), each half running the 5-step
// fused pipeline: smax -> reduce -> sexp -> reduce -> scaled P@V.
// ---------------------------------------------------------------------------
extern "C" void kernel_launch(void* const* d_in, const int* in_sizes, int n_in,
                              void* d_out, int out_size) {
    const float* x  = (const float*)d_in[0];
    const float* Wk = (const float*)d_in[1];
    const float* Wq = (const float*)d_in[2];
    const float* Wv = (const float*)d_in[3];
    float* out = (float*)d_out;

    static cudaStream_t s2 = nullptr, s3 = nullptr;
    static cudaEvent_t evX = nullptr, evV = nullptr, evQK = nullptr, ev3 = nullptr;
    if (!s2) {
        cudaStreamCreateWithFlags(&s2, cudaStreamNonBlocking);
        cudaStreamCreateWithFlags(&s3, cudaStreamNonBlocking);
        cudaEventCreateWithFlags(&evX, cudaEventDisableTiming);
        cudaEventCreateWithFlags(&evV, cudaEventDisableTiming);
        cudaEventCreateWithFlags(&evQK, cudaEventDisableTiming);
        cudaEventCreateWithFlags(&ev3, cudaEventDisableTiming);
    }

    __half *xA2, *xhi, *wqkB2, *wvh, *qA2, *kB2, *vh, *ph;
    float *maxpart, *sumpart, *rowmax, *rowinv;
    cudaGetSymbolAddress((void**)&xA2, g_xA2);
    cudaGetSymbolAddress((void**)&xhi, g_xhi);
    cudaGetSymbolAddress((void**)&wqkB2, g_wqkB2);
    cudaGetSymbolAddress((void**)&wvh, g_wvh);
    cudaGetSymbolAddress((void**)&qA2, g_qA2);
    cudaGetSymbolAddress((void**)&kB2, g_kB2);
    cudaGetSymbolAddress((void**)&vh, g_vh);
    cudaGetSymbolAddress((void**)&ph, g_ph);
    cudaGetSymbolAddress((void**)&maxpart, g_maxpart);
    cudaGetSymbolAddress((void**)&sumpart, g_sumpart);
    cudaGetSymbolAddress((void**)&rowmax, g_rowmax);
    cudaGetSymbolAddress((void**)&rowinv, g_rowinv);

    cudaFuncSetAttribute((const void*)gemm_hmma<2, false, 0>, cudaFuncAttributeMaxDynamicSharedMemorySize, GSMEM);
    cudaFuncSetAttribute((const void*)gemm_hmma<1, false, 0>, cudaFuncAttributeMaxDynamicSharedMemorySize, GSMEM);
    cudaFuncSetAttribute((const void*)gemm_hmma<3, true,  0>, cudaFuncAttributeMaxDynamicSharedMemorySize, GSMEM);
    cudaFuncSetAttribute((const void*)gemm_hmma<4, true,  0>, cudaFuncAttributeMaxDynamicSharedMemorySize, GSMEM);
    cudaFuncSetAttribute((const void*)gemm_hmma<5, false, 2>, cudaFuncAttributeMaxDynamicSharedMemorySize, GSMEM);

    // ---- legacy: packs ----
    packW2<<<(128 * D + 255) / 256, 256>>>(Wq, Wk, wqkB2);
    pack_x<<<(MTOT * D + 255) / 256, 256>>>(x, xA2, xhi);
    cudaEventRecord(evX, 0);

    // ---- s2: V path ----
    cudaStreamWaitEvent(s2, evX, 0);
    packHi<<<(D * D + 255) / 256, 256, 0, s2>>>(Wv, wvh, D * D);
    gemm_hmma<1, false, 0><<<dim3(MTOT / 128, D / 128, 1), 256, GSMEM, s2>>>(
        wvh, xhi, vh, D, D, MTOT, 16, 0, 0, 0, 0, nullptr, nullptr);
    cudaEventRecord(evV, s2);

    // ---- legacy: fused QK projection (writes qA2 + kB2 directly) ----
    gemm_hmma<2, false, 0><<<dim3(1, MTOT / 128, 1), 256, GSMEM>>>(
        xA2, wqkB2, nullptr, 2 * D, 2 * D, 0, 32, 1024, 1024, 0, 0, nullptr, nullptr);
    cudaEventRecord(evQK, 0);

    const size_t sQ = (size_t)T * 128;
    const int nRB = (BATCH * (T / 2) + 255) / 256;

    // ---- s3: light half0 (row tiles 0..15) ----
    cudaStreamWaitEvent(s3, evQK, 0);
    gemm_hmma<3, true, 0><<<dim3(16, 16, BATCH), 256, GSMEM, s3>>>(
        qA2, kB2, nullptr, 128, 128, 0, 2, sQ, sQ, 0, 0, nullptr, maxpart);
    reduce_rows<<<nRB, 256, 0, s3>>>(maxpart, rowmax, 0, 0);
    gemm_hmma<4, true, 0><<<dim3(16, 16, BATCH), 256, GSMEM, s3>>>(
        qA2, kB2, ph, 128, 128, T, 2, sQ, sQ, (size_t)T * T, 0, rowmax, sumpart);
    reduce_rows<<<nRB, 256, 0, s3>>>(sumpart, rowinv, 0, 1);
    cudaStreamWaitEvent(s3, evV, 0);
    gemm_hmma<5, false, 2><<<dim3(D / 128, 16, BATCH), 256, GSMEM, s3>>>(
        ph, vh, out, T, MTOT, D, T / 64,
        (size_t)T * T, (size_t)T, (size_t)T * D, 0, rowinv, nullptr);
    cudaEventRecord(ev3, s3);

    // ---- legacy: heavy half1 (row tiles 16..31) ----
    gemm_hmma<3, true, 0><<<dim3(32, 16, BATCH), 256, GSMEM>>>(
        qA2, kB2, nullptr, 128, 128, 0, 2, sQ, sQ, 0, 16, nullptr, maxpart);
    reduce_rows<<<nRB, 256>>>(maxpart, rowmax, T / 2, 0);
    gemm_hmma<4, true, 0><<<dim3(32, 16, BATCH), 256, GSMEM>>>(
        qA2, kB2, ph, 128, 128, T, 2, sQ, sQ, (size_t)T * T, 16, rowmax, sumpart);
    reduce_rows<<<nRB, 256>>>(sumpart, rowinv, T / 2, 1);
    cudaStreamWaitEvent(0, evV, 0);
    gemm_hmma<5, false, 2><<<dim3(D / 128, 16, BATCH), 256, GSMEM>>>(
        ph, vh, out, T, MTOT, D, T / 64,
        (size_t)T * T, (size_t)T, (size_t)T * D, 16, rowinv, nullptr);

    // ---- join ----
    cudaStreamWaitEvent(0, ev3, 0);
}